// round 5
// baseline (speedup 1.0000x reference)
#include <cuda_runtime.h>
#include <math.h>

// Problem constants
#define BB   64
#define TMEL 2000
#define EE   512
#define MMI  80
#define PP   256
#define HH   1024
#define TD   1000
#define RR   (TD*BB)   // 64000 rows

// ---------------- static device scratch (allocation-free rule) ----------------
__device__ float g_di [(size_t)RR*MMI];     // teacher-forced prenet input
__device__ float g_mem[(size_t)RR*EE];      // pooled memory  [t][b][512]
__device__ float g_xa [(size_t)RR*PP];
__device__ float g_xb [(size_t)RR*PP];
__device__ float g_gi [(size_t)RR*3*HH];    // precomputed input gates (reused per pass)
__device__ float g_h1 [(size_t)RR*HH];
__device__ float g_h2 [(size_t)RR*HH];
__device__ float g_h3 [(size_t)RR*HH];
__device__ float g_d2 [(size_t)RR*HH];      // d2, later r3
__device__ float g_r2 [(size_t)RR*HH];

// software grid barrier state (zero-initialized at module load; invariant:
// g_barcnt returns to 0 after every barrier, g_bargen monotonically increments)
__device__ unsigned g_barcnt;
__device__ unsigned g_bargen;

// ---------------- prep kernels ----------------
__global__ void pool_kernel(const float* __restrict__ memorys)
{
    // g_mem[t][b][e] = 0.5*(memorys[b][2t][e] + memorys[b][2t+1][e])
    size_t total = (size_t)RR * EE;
    for (size_t i = (size_t)blockIdx.x*blockDim.x + threadIdx.x; i < total;
         i += (size_t)gridDim.x*blockDim.x) {
        int e = (int)(i % EE);
        int tb = (int)(i / EE);
        int b = tb & (BB-1);
        int t = tb >> 6;
        const float* src = memorys + ((size_t)b*TMEL + 2*t)*EE + e;
        g_mem[i] = 0.5f*(src[0] + src[EE]);
    }
}

__global__ void di_kernel(const float* __restrict__ dec)
{
    // g_di[t][b][m] = (t==0) ? 0 : dec[b][2t-1][m]
    size_t total = (size_t)RR * MMI;
    for (size_t i = (size_t)blockIdx.x*blockDim.x + threadIdx.x; i < total;
         i += (size_t)gridDim.x*blockDim.x) {
        int m = (int)(i % MMI);
        int tb = (int)(i / MMI);
        int b = tb & (BB-1);
        int t = tb >> 6;
        g_di[i] = (t == 0) ? 0.0f : dec[((size_t)b*TMEL + (2*t-1))*MMI + m];
    }
}

__global__ void add_kernel(const float* __restrict__ a, const float* __restrict__ b,
                           float* __restrict__ c, size_t n)
{
    for (size_t i = (size_t)blockIdx.x*blockDim.x + threadIdx.x; i < n;
         i += (size_t)gridDim.x*blockDim.x)
        c[i] = a[i] + b[i];
}

// ---------------- generic fused GEMM:  C = concat(A1,A2) @ W^T + bias ----------------
// A1:[RR,K1], A2:[RR,K2] (optional), W:[N,K1+K2] row-major, tile 128x128x8, 8x8/thread.
__global__ __launch_bounds__(256)
void gemm128(const float* __restrict__ A1, int K1,
             const float* __restrict__ A2, int K2,
             const float* __restrict__ W,  const float* __restrict__ bias,
             float* __restrict__ C, int N, int doRelu, int outBT)
{
    __shared__ float As[8][132];
    __shared__ float Ws[8][132];
    const int K = K1 + K2;
    const int tid  = threadIdx.x;
    const int row0 = blockIdx.y * 128;
    const int n0   = blockIdx.x * 128;
    const int ty = tid >> 4, tx = tid & 15;
    const int lm = tid >> 1;          // 0..127
    const int lk = (tid & 1) * 4;     // 0 or 4

    float acc[8][8];
#pragma unroll
    for (int i = 0; i < 8; i++)
#pragma unroll
        for (int j = 0; j < 8; j++) acc[i][j] = 0.0f;

    for (int kc = 0; kc < K; kc += 8) {
        int k = kc + lk;
        float4 av;
        if (k < K1) av = *(const float4*)(A1 + (size_t)(row0+lm)*K1 + k);
        else        av = *(const float4*)(A2 + (size_t)(row0+lm)*K2 + (k - K1));
        float4 wv = make_float4(0.f,0.f,0.f,0.f);
        int nr = n0 + lm;
        if (nr < N) wv = *(const float4*)(W + (size_t)nr*K + k);

        As[lk+0][lm]=av.x; As[lk+1][lm]=av.y; As[lk+2][lm]=av.z; As[lk+3][lm]=av.w;
        Ws[lk+0][lm]=wv.x; Ws[lk+1][lm]=wv.y; Ws[lk+2][lm]=wv.z; Ws[lk+3][lm]=wv.w;
        __syncthreads();
#pragma unroll
        for (int kk = 0; kk < 8; kk++) {
            float a[8], w[8];
#pragma unroll
            for (int i = 0; i < 8; i++) a[i] = As[kk][ty*8+i];
#pragma unroll
            for (int j = 0; j < 8; j++) w[j] = Ws[kk][tx*8+j];
#pragma unroll
            for (int i = 0; i < 8; i++)
#pragma unroll
                for (int j = 0; j < 8; j++)
                    acc[i][j] = fmaf(a[i], w[j], acc[i][j]);
        }
        __syncthreads();
    }

#pragma unroll
    for (int i = 0; i < 8; i++) {
        int m = row0 + ty*8 + i;
#pragma unroll
        for (int j = 0; j < 8; j++) {
            int n = n0 + tx*8 + j;
            if (n < N) {
                float v = acc[i][j] + bias[n];
                if (doRelu) v = fmaxf(v, 0.0f);
                if (outBT) {
                    int t = m >> 6, b = m & (BB-1);
                    C[((size_t)b*TD + t)*N + n] = v;
                } else {
                    C[(size_t)m*N + n] = v;
                }
            }
        }
    }
}

// ---------------- persistent GRU recurrence pass ----------------
// One launch per GRU pass. 128 CTAs (co-resident on 148 SMs) loop over all
// timesteps with a software grid barrier between steps.
// Per step: gh = h_prev @ whh^T + bhh, then fused GRU nonlinearity with
// precomputed input gates gi.
__device__ __forceinline__ float sigmoidf(float x) { return 1.0f/(1.0f + expf(-x)); }

#define GRU_NBLK 128

__device__ __forceinline__ void grid_barrier()
{
    __syncthreads();
    if (threadIdx.x == 0) {
        __threadfence();
        unsigned g = *(volatile unsigned*)&g_bargen;
        unsigned old = atomicAdd(&g_barcnt, 1u);
        if (old == GRU_NBLK - 1u) {
            atomicExch(&g_barcnt, 0u);
            __threadfence();
            atomicAdd(&g_bargen, 1u);
        } else {
            while (*(volatile unsigned*)&g_bargen == g) { }
        }
        __threadfence();
    }
    __syncthreads();
}

__global__ __launch_bounds__(384, 1)
void gru_pass(int pass, const float* __restrict__ whh, const float* __restrict__ bhh)
{
    float* hall = (pass == 0) ? g_h1 : (pass == 1) ? g_h2 : g_h3;

    extern __shared__ float sm[];
    float* hs  = sm;              // [128][68]  staged h chunk  (34816 B)
    float* ws  = sm + 128*68;     // [128][24]  staged w chunk  (12288 B)
    float* red = sm;              // [8][24][64] reduction      (49152 B, aliased)

    const int tid = threadIdx.x;               // 384
    const int j0  = blockIdx.x * 8;
    const int bg  = tid & 7;                   // 8 groups of 8 batch rows
    const int rg  = (tid >> 3) % 6;            // 6 groups of 4 gate rows
    const int ks  = tid / 48;                  // 8-way K split

    for (int t = 0; t < TD; t++) {
        const float* gi    = g_gi + (size_t)t * BB * 3 * HH;
        const float* hprev = hall + (size_t)(t-1) * BB * HH;   // unused when t==0
        float*       hout  = hall + (size_t)t * BB * HH;

        float acc[4][8];
#pragma unroll
        for (int r = 0; r < 4; r++)
#pragma unroll
            for (int i = 0; i < 8; i++) acc[r][i] = 0.0f;

        if (t > 0) {
            for (int kc = 0; kc < HH; kc += 128) {
                __syncthreads();
                // stage h chunk transposed: hs[k][b]
                for (int e = tid; e < 64*128; e += 384) {
                    int b = e >> 7, kk = e & 127;
                    hs[kk*68 + b] = hprev[(size_t)b*HH + kc + kk];
                }
                // stage 24 weight rows transposed: ws[k][lr]
                for (int e = tid; e < 24*128; e += 384) {
                    int lr = e >> 7, kk = e & 127;
                    int g = lr >> 3, jj = lr & 7;
                    ws[kk*24 + lr] = whh[(size_t)(g*HH + j0 + jj)*HH + kc + kk];
                }
                __syncthreads();
                const int kbase = ks * 16;
#pragma unroll
                for (int ki = 0; ki < 16; ki++) {
                    const float* hp = hs + (kbase + ki)*68 + bg*8;
                    const float* wp = ws + (kbase + ki)*24 + rg*4;
                    float hv[8], wv[4];
#pragma unroll
                    for (int i = 0; i < 8; i++) hv[i] = hp[i];
#pragma unroll
                    for (int r = 0; r < 4; r++) wv[r] = wp[r];
#pragma unroll
                    for (int r = 0; r < 4; r++)
#pragma unroll
                        for (int i = 0; i < 8; i++)
                            acc[r][i] = fmaf(wv[r], hv[i], acc[r][i]);
                }
            }
        }
        __syncthreads();
        // write K-split partials: red[ks][lr][b]
#pragma unroll
        for (int r = 0; r < 4; r++)
#pragma unroll
            for (int i = 0; i < 8; i++)
                red[((size_t)ks*24 + rg*4 + r)*64 + bg*8 + i] = acc[r][i];
        __syncthreads();
        // reduce 8 slices + bhh -> red[0][lr][b]
        for (int o = tid; o < 24*64; o += 384) {
            int lr = o >> 6, b = o & 63;
            float s = bhh[(lr >> 3)*HH + j0 + (lr & 7)];
#pragma unroll
            for (int q = 0; q < 8; q++) s += red[((size_t)q*24 + lr)*64 + b];
            red[(size_t)lr*64 + b] = s;
        }
        __syncthreads();
        // fused GRU update (gate order r, z, n)
        for (int o = tid; o < 8*64; o += 384) {
            int jj = o >> 6, b = o & 63;
            int j = j0 + jj;
            float gr = red[(size_t)(jj     )*64 + b];
            float gz = red[(size_t)(8  + jj)*64 + b];
            float gn = red[(size_t)(16 + jj)*64 + b];
            const float* gib = gi + (size_t)b*3*HH;
            float r  = sigmoidf(gib[j]        + gr);
            float z  = sigmoidf(gib[HH  + j]  + gz);
            float n  = tanhf   (gib[2*HH + j] + r*gn);
            float hp = (t > 0) ? hprev[(size_t)b*HH + j] : 0.0f;
            hout[(size_t)b*HH + j] = (1.0f - z)*n + z*hp;
        }
        // all CTAs must finish step t before any reads hout as hprev at t+1
        grid_barrier();
    }
}

// ---------------- host orchestration ----------------
extern "C" void kernel_launch(void* const* d_in, const int* in_sizes, int n_in,
                              void* d_out, int out_size)
{
    const float* memorys = (const float*)d_in[0];
    const float* dec     = (const float*)d_in[1];
    // d_in[2] memory_lengths: unused by reference decode path
    const float* pre_w1 = (const float*)d_in[3];
    const float* pre_b1 = (const float*)d_in[4];
    const float* pre_w2 = (const float*)d_in[5];
    const float* pre_b2 = (const float*)d_in[6];
    const float* g1_wih = (const float*)d_in[7];
    const float* g1_whh = (const float*)d_in[8];
    const float* g1_bih = (const float*)d_in[9];
    const float* g1_bhh = (const float*)d_in[10];
    const float* att_w  = (const float*)d_in[11];
    const float* att_b  = (const float*)d_in[12];
    const float* g2_wih = (const float*)d_in[13];
    const float* g2_whh = (const float*)d_in[14];
    const float* g2_bih = (const float*)d_in[15];
    const float* g2_bhh = (const float*)d_in[16];
    const float* g3_wih = (const float*)d_in[17];
    const float* g3_whh = (const float*)d_in[18];
    const float* g3_bih = (const float*)d_in[19];
    const float* g3_bhh = (const float*)d_in[20];
    const float* proj_w = (const float*)d_in[21];
    const float* proj_b = (const float*)d_in[22];
    float* out = (float*)d_out;

    float *p_di,*p_mem,*p_xa,*p_xb,*p_gi,*p_h1,*p_h2,*p_h3,*p_d2,*p_r2;
    cudaGetSymbolAddress((void**)&p_di,  g_di);
    cudaGetSymbolAddress((void**)&p_mem, g_mem);
    cudaGetSymbolAddress((void**)&p_xa,  g_xa);
    cudaGetSymbolAddress((void**)&p_xb,  g_xb);
    cudaGetSymbolAddress((void**)&p_gi,  g_gi);
    cudaGetSymbolAddress((void**)&p_h1,  g_h1);
    cudaGetSymbolAddress((void**)&p_h2,  g_h2);
    cudaGetSymbolAddress((void**)&p_h3,  g_h3);
    cudaGetSymbolAddress((void**)&p_d2,  g_d2);
    cudaGetSymbolAddress((void**)&p_r2,  g_r2);

    cudaFuncSetAttribute(gru_pass, cudaFuncAttributeMaxDynamicSharedMemorySize, 64*1024);
    const int GRU_SMEM = 8*24*64*4;   // 49152 B (>= staging 47104 B)

    // prep
    pool_kernel<<<4096, 256>>>(memorys);
    di_kernel  <<<4096, 256>>>(dec);

    auto gemm = [&](const float* A1, int K1, const float* A2, int K2,
                    const float* W, const float* b, float* C, int N,
                    int relu, int bt) {
        dim3 grid((N + 127)/128, RR/128);
        gemm128<<<grid, 256>>>(A1, K1, A2, K2, W, b, C, N, relu, bt);
    };

    // prenet
    gemm(p_di, MMI, nullptr, 0, pre_w1, pre_b1, p_xa, PP, 1, 0);
    gemm(p_xa, PP,  nullptr, 0, pre_w2, pre_b2, p_xb, PP, 1, 0);

    // GRU1 input gates (batched over all timesteps) + recurrence
    gemm(p_xb, PP, p_mem, EE, g1_wih, g1_bih, p_gi, 3*HH, 0, 0);
    gru_pass<<<GRU_NBLK, 384, GRU_SMEM>>>(0, g1_whh, g1_bhh);

    // attention linear + GRU2 input gates (batched) + recurrence
    gemm(p_h1, HH, p_mem, EE, att_w, att_b, p_d2, HH, 0, 0);
    gemm(p_d2, HH, nullptr, 0, g2_wih, g2_bih, p_gi, 3*HH, 0, 0);
    gru_pass<<<GRU_NBLK, 384, GRU_SMEM>>>(1, g2_whh, g2_bhh);

    // r2 = h2 + d2
    add_kernel<<<8192, 256>>>(p_h2, p_d2, p_r2, (size_t)RR*HH);

    // GRU3 input gates (batched) + recurrence
    gemm(p_r2, HH, nullptr, 0, g3_wih, g3_bih, p_gi, 3*HH, 0, 0);
    gru_pass<<<GRU_NBLK, 384, GRU_SMEM>>>(2, g3_whh, g3_bhh);

    // r3 = h3 + r2 (into g_d2)
    add_kernel<<<8192, 256>>>(p_h3, p_r2, p_d2, (size_t)RR*HH);

    // projection, writing directly in [B,T,160] layout
    gemm(p_d2, HH, p_mem, EE, proj_w, proj_b, out, MMI*2, 0, 1);
}

// round 9
// speedup vs baseline: 2.4611x; 2.4611x over previous
#include <cuda_runtime.h>
#include <cuda_bf16.h>
#include <math.h>
#include <stdint.h>

#define BB   64
#define TMEL 2000
#define EE   512
#define MMI  80
#define PP   256
#define HH   1024
#define TD   1000
#define RR   (TD*BB)

#define GRU_NBLK 128

// ---------------- static device scratch (allocation-free rule) ----------------
__device__ float g_di [(size_t)RR*MMI];
__device__ float g_mem[(size_t)RR*EE];
__device__ float g_xa [(size_t)RR*PP];
__device__ float g_xb [(size_t)RR*PP];
__device__ float g_gi [(size_t)RR*3*HH];
__device__ float g_h1 [(size_t)RR*HH];
__device__ float g_h2 [(size_t)RR*HH];
__device__ float g_h3 [(size_t)RR*HH];
__device__ float g_d2 [(size_t)RR*HH];
__device__ float g_r2 [(size_t)RR*HH];

// mma-fragment-packed recurrent weights: [c(128)][w(8)][q(8)][nt(3)][lane(32)]
// each entry: uint4 {bhi0, bhi1, blo0, blo1}  (12.58 MB)
__device__ __align__(16) uint4 g_wfrag[(size_t)128*8*8*3*32];
// mma-A-fragment-packed h (hi+lo), ping-pong:
// [par(2)][m(4)][s(64)] : 32 lanes x 32B  ->  64 uint4 per tile  (512 KB)
__device__ __align__(16) uint4 g_hfrag[(size_t)2*4*64*64];

__device__ unsigned g_barcnt;
__device__ unsigned g_bargen;

// ---------------- prep kernels ----------------
__global__ void pool_kernel(const float* __restrict__ memorys)
{
    size_t total = (size_t)RR * EE;
    for (size_t i = (size_t)blockIdx.x*blockDim.x + threadIdx.x; i < total;
         i += (size_t)gridDim.x*blockDim.x) {
        int e = (int)(i % EE);
        int tb = (int)(i / EE);
        int b = tb & (BB-1);
        int t = tb >> 6;
        const float* src = memorys + ((size_t)b*TMEL + 2*t)*EE + e;
        g_mem[i] = 0.5f*(src[0] + src[EE]);
    }
}

__global__ void di_kernel(const float* __restrict__ dec)
{
    size_t total = (size_t)RR * MMI;
    for (size_t i = (size_t)blockIdx.x*blockDim.x + threadIdx.x; i < total;
         i += (size_t)gridDim.x*blockDim.x) {
        int m = (int)(i % MMI);
        int tb = (int)(i / MMI);
        int b = tb & (BB-1);
        int t = tb >> 6;
        g_di[i] = (t == 0) ? 0.0f : dec[((size_t)b*TMEL + (2*t-1))*MMI + m];
    }
}

__global__ void add_kernel(const float* __restrict__ a, const float* __restrict__ b,
                           float* __restrict__ c, size_t n)
{
    for (size_t i = (size_t)blockIdx.x*blockDim.x + threadIdx.x; i < n;
         i += (size_t)gridDim.x*blockDim.x)
        c[i] = a[i] + b[i];
}

__device__ __forceinline__ uint32_t pack_bf2(float lo, float hi)
{
    __nv_bfloat162 t = __floats2bfloat162_rn(lo, hi);   // .x in low 16 bits
    return *(uint32_t*)&t;
}

// pack whh into per-lane B fragments (bf16 hi/lo split), mma m16n8k16 col-major B.
// B[k][n] = whh[nt*HH + 8c + n][w*128 + q*16 + k]
__global__ void wfrag_prep(const float* __restrict__ whh)
{
    size_t idx = (size_t)blockIdx.x*blockDim.x + threadIdx.x;
    if (idx >= (size_t)128*8*8*3*32) return;
    int lane = (int)(idx & 31);
    size_t r1 = idx >> 5;
    int nt = (int)(r1 % 3);
    size_t r2 = r1 / 3;
    int q = (int)(r2 & 7);
    int w = (int)((r2 >> 3) & 7);
    int c = (int)(r2 >> 6);
    int gid = lane >> 2, tig = lane & 3;
    const float* wp = whh + (size_t)(nt*HH + c*8 + gid)*HH + w*128 + q*16;
    float v0 = wp[2*tig], v1 = wp[2*tig+1], v2 = wp[2*tig+8], v3 = wp[2*tig+9];
    float h0 = __bfloat162float(__float2bfloat16(v0));
    float h1 = __bfloat162float(__float2bfloat16(v1));
    float h2 = __bfloat162float(__float2bfloat16(v2));
    float h3 = __bfloat162float(__float2bfloat16(v3));
    uint4 o;
    o.x = pack_bf2(v0, v1);
    o.y = pack_bf2(v2, v3);
    o.z = pack_bf2(v0 - h0, v1 - h1);
    o.w = pack_bf2(v2 - h2, v3 - h3);
    g_wfrag[idx] = o;
}

__global__ void hfrag_zero()
{
    int i = blockIdx.x*blockDim.x + threadIdx.x;
    if (i < 4*64*64) g_hfrag[i] = make_uint4(0u,0u,0u,0u);   // parity-0 slice
}

// ---------------- generic fused SIMT GEMM (known-good) ----------------
__global__ __launch_bounds__(256)
void gemm128(const float* __restrict__ A1, int K1,
             const float* __restrict__ A2, int K2,
             const float* __restrict__ W,  const float* __restrict__ bias,
             float* __restrict__ C, int N, int doRelu, int outBT)
{
    __shared__ float As[8][132];
    __shared__ float Ws[8][132];
    const int K = K1 + K2;
    const int tid  = threadIdx.x;
    const int row0 = blockIdx.y * 128;
    const int n0   = blockIdx.x * 128;
    const int ty = tid >> 4, tx = tid & 15;
    const int lm = tid >> 1;
    const int lk = (tid & 1) * 4;

    float acc[8][8];
#pragma unroll
    for (int i = 0; i < 8; i++)
#pragma unroll
        for (int j = 0; j < 8; j++) acc[i][j] = 0.0f;

    for (int kc = 0; kc < K; kc += 8) {
        int k = kc + lk;
        float4 av;
        if (k < K1) av = *(const float4*)(A1 + (size_t)(row0+lm)*K1 + k);
        else        av = *(const float4*)(A2 + (size_t)(row0+lm)*K2 + (k - K1));
        float4 wv = make_float4(0.f,0.f,0.f,0.f);
        int nr = n0 + lm;
        if (nr < N) wv = *(const float4*)(W + (size_t)nr*K + k);

        As[lk+0][lm]=av.x; As[lk+1][lm]=av.y; As[lk+2][lm]=av.z; As[lk+3][lm]=av.w;
        Ws[lk+0][lm]=wv.x; Ws[lk+1][lm]=wv.y; Ws[lk+2][lm]=wv.z; Ws[lk+3][lm]=wv.w;
        __syncthreads();
#pragma unroll
        for (int kk = 0; kk < 8; kk++) {
            float a[8], w[8];
#pragma unroll
            for (int i = 0; i < 8; i++) a[i] = As[kk][ty*8+i];
#pragma unroll
            for (int j = 0; j < 8; j++) w[j] = Ws[kk][tx*8+j];
#pragma unroll
            for (int i = 0; i < 8; i++)
#pragma unroll
                for (int j = 0; j < 8; j++)
                    acc[i][j] = fmaf(a[i], w[j], acc[i][j]);
        }
        __syncthreads();
    }

#pragma unroll
    for (int i = 0; i < 8; i++) {
        int m = row0 + ty*8 + i;
#pragma unroll
        for (int j = 0; j < 8; j++) {
            int n = n0 + tx*8 + j;
            if (n < N) {
                float v = acc[i][j] + bias[n];
                if (doRelu) v = fmaxf(v, 0.0f);
                if (outBT) {
                    int t = m >> 6, b = m & (BB-1);
                    C[((size_t)b*TD + t)*N + n] = v;
                } else {
                    C[(size_t)m*N + n] = v;
                }
            }
        }
    }
}

// ---------------- persistent mma.sync GRU recurrence ----------------
__device__ __forceinline__ float sigmoidf(float x) { return 1.0f/(1.0f + expf(-x)); }

__device__ __forceinline__ void grid_barrier()
{
    __threadfence();
    __syncthreads();
    if (threadIdx.x == 0) {
        unsigned g = *(volatile unsigned*)&g_bargen;
        unsigned old = atomicAdd(&g_barcnt, 1u);
        if (old == GRU_NBLK - 1u) {
            atomicExch(&g_barcnt, 0u);
            __threadfence();
            atomicAdd(&g_bargen, 1u);
        } else {
            while (*(volatile unsigned*)&g_bargen == g) { }
        }
        __threadfence();
    }
    __syncthreads();
}

__device__ __forceinline__ void mma16816(float* c,
    uint32_t a0, uint32_t a1, uint32_t a2, uint32_t a3,
    uint32_t b0, uint32_t b1)
{
    asm volatile(
        "mma.sync.aligned.m16n8k16.row.col.f32.bf16.bf16.f32 "
        "{%0,%1,%2,%3}, {%4,%5,%6,%7}, {%8,%9}, {%0,%1,%2,%3};"
        : "+f"(c[0]), "+f"(c[1]), "+f"(c[2]), "+f"(c[3])
        : "r"(a0), "r"(a1), "r"(a2), "r"(a3), "r"(b0), "r"(b1));
}

// Each CTA c owns hidden cols [8c, 8c+8) -> 24 gate rows (3 n8 tiles).
// gh^T layout as mma: M=64 batch (4 m16 tiles), N=24 gate rows, K=1024
// (8 warps, 128 K each), bf16 3-term split, fp32 accum, smem cross-warp reduce.
__global__ __launch_bounds__(256, 1)
void gru_pass(int pass, const float* __restrict__ bhh)
{
    float* hall = (pass == 0) ? g_h1 : (pass == 1) ? g_h2 : g_h3;
    __shared__ float sred[12288];     // [w][m][nt][reg][lane]  = 48 KB
    const int tid = threadIdx.x, wid = tid >> 5, lane = tid & 31;
    const int c = blockIdx.x;
    const uint4* wbase = g_wfrag + ((size_t)(c*8 + wid)*8)*3*32;

    for (int t = 0; t < TD; t++) {
        const int par = t & 1;
        const uint4* hbase = g_hfrag + (size_t)par*4*64*64;

        float acc[4][3][4];
#pragma unroll
        for (int m = 0; m < 4; m++)
#pragma unroll
            for (int nt = 0; nt < 3; nt++)
#pragma unroll
                for (int r = 0; r < 4; r++) acc[m][nt][r] = 0.0f;

#pragma unroll 2
        for (int q = 0; q < 8; q++) {
            const int s = wid*8 + q;
            uint4 ah[4], al[4];
#pragma unroll
            for (int m = 0; m < 4; m++) {
                const uint4* p = hbase + ((size_t)m*64 + s)*64 + lane*2;
                ah[m] = p[0];
                al[m] = p[1];
            }
            uint4 bw[3];
#pragma unroll
            for (int nt = 0; nt < 3; nt++)
                bw[nt] = wbase[(q*3 + nt)*32 + lane];
#pragma unroll
            for (int m = 0; m < 4; m++)
#pragma unroll
                for (int nt = 0; nt < 3; nt++) {
                    mma16816(acc[m][nt], ah[m].x, ah[m].y, ah[m].z, ah[m].w, bw[nt].x, bw[nt].y);
                    mma16816(acc[m][nt], ah[m].x, ah[m].y, ah[m].z, ah[m].w, bw[nt].z, bw[nt].w);
                    mma16816(acc[m][nt], al[m].x, al[m].y, al[m].z, al[m].w, bw[nt].x, bw[nt].y);
                }
        }
        // cross-warp partials to smem
#pragma unroll
        for (int m = 0; m < 4; m++)
#pragma unroll
            for (int nt = 0; nt < 3; nt++)
#pragma unroll
                for (int r = 0; r < 4; r++)
                    sred[(((wid*4 + m)*3 + nt)*4 + r)*32 + lane] = acc[m][nt][r];
        __syncthreads();

        // epilogue: 512 (b, j) pairs, reduce 8 warps, GRU update, write h + frags
        const int par2 = (t + 1) & 1;
        for (int o = tid; o < 512; o += 256) {
            int b = o >> 3, j = o & 7;
            int jg = c*8 + j;
            int m = b >> 4;
            int rowhi = (b >> 3) & 1;
            int lo_ = (b & 7)*4 + (j >> 1);
            int rc = rowhi*2 + (j & 1);
            float gsum[3];
#pragma unroll
            for (int nt = 0; nt < 3; nt++) {
                float s_ = 0.0f;
#pragma unroll
                for (int w = 0; w < 8; w++)
                    s_ += sred[(((w*4 + m)*3 + nt)*4 + rc)*32 + lo_];
                gsum[nt] = s_;
            }
            const float* gib = g_gi + ((size_t)t*BB + b)*3*HH;
            float rr = sigmoidf(gib[jg]        + gsum[0] + bhh[jg]);
            float zz = sigmoidf(gib[HH + jg]   + gsum[1] + bhh[HH + jg]);
            float nn = tanhf   (gib[2*HH + jg] + rr*(gsum[2] + bhh[2*HH + jg]));
            float hp = (t > 0) ? hall[((size_t)(t-1)*BB + b)*HH + jg] : 0.0f;
            float h  = (1.0f - zz)*nn + zz*hp;
            hall[((size_t)t*BB + b)*HH + jg] = h;

            // write h into A-fragment layout (hi at reg 0..3, lo at reg 4..7)
            __nv_bfloat16 hhi = __float2bfloat16(h);
            __nv_bfloat16 hlo = __float2bfloat16(h - __bfloat162float(hhi));
            int s = jg >> 4;
            int colhi = c & 1;              // (jg & 15) >> 3
            int reg = rowhi + 2*colhi;
            uint8_t* base = (uint8_t*)g_hfrag
                + (((size_t)par2*4 + m)*64 + s)*1024 + lo_*32;
            *(__nv_bfloat16*)(base + reg*4 + (j & 1)*2)      = hhi;
            *(__nv_bfloat16*)(base + 16 + reg*4 + (j & 1)*2) = hlo;
        }
        grid_barrier();
    }
}

// ---------------- host orchestration ----------------
extern "C" void kernel_launch(void* const* d_in, const int* in_sizes, int n_in,
                              void* d_out, int out_size)
{
    const float* memorys = (const float*)d_in[0];
    const float* dec     = (const float*)d_in[1];
    const float* pre_w1 = (const float*)d_in[3];
    const float* pre_b1 = (const float*)d_in[4];
    const float* pre_w2 = (const float*)d_in[5];
    const float* pre_b2 = (const float*)d_in[6];
    const float* g1_wih = (const float*)d_in[7];
    const float* g1_whh = (const float*)d_in[8];
    const float* g1_bih = (const float*)d_in[9];
    const float* g1_bhh = (const float*)d_in[10];
    const float* att_w  = (const float*)d_in[11];
    const float* att_b  = (const float*)d_in[12];
    const float* g2_wih = (const float*)d_in[13];
    const float* g2_whh = (const float*)d_in[14];
    const float* g2_bih = (const float*)d_in[15];
    const float* g2_bhh = (const float*)d_in[16];
    const float* g3_wih = (const float*)d_in[17];
    const float* g3_whh = (const float*)d_in[18];
    const float* g3_bih = (const float*)d_in[19];
    const float* g3_bhh = (const float*)d_in[20];
    const float* proj_w = (const float*)d_in[21];
    const float* proj_b = (const float*)d_in[22];
    float* out = (float*)d_out;

    float *p_di,*p_mem,*p_xa,*p_xb,*p_gi,*p_h1,*p_h2,*p_h3,*p_d2,*p_r2;
    cudaGetSymbolAddress((void**)&p_di,  g_di);
    cudaGetSymbolAddress((void**)&p_mem, g_mem);
    cudaGetSymbolAddress((void**)&p_xa,  g_xa);
    cudaGetSymbolAddress((void**)&p_xb,  g_xb);
    cudaGetSymbolAddress((void**)&p_gi,  g_gi);
    cudaGetSymbolAddress((void**)&p_h1,  g_h1);
    cudaGetSymbolAddress((void**)&p_h2,  g_h2);
    cudaGetSymbolAddress((void**)&p_h3,  g_h3);
    cudaGetSymbolAddress((void**)&p_d2,  g_d2);
    cudaGetSymbolAddress((void**)&p_r2,  g_r2);

    pool_kernel<<<4096, 256>>>(memorys);
    di_kernel  <<<4096, 256>>>(dec);

    auto gemm = [&](const float* A1, int K1, const float* A2, int K2,
                    const float* W, const float* b, float* C, int N,
                    int relu, int bt) {
        dim3 grid((N + 127)/128, RR/128);
        gemm128<<<grid, 256>>>(A1, K1, A2, K2, W, b, C, N, relu, bt);
    };

    // prenet
    gemm(p_di, MMI, nullptr, 0, pre_w1, pre_b1, p_xa, PP, 1, 0);
    gemm(p_xa, PP,  nullptr, 0, pre_w2, pre_b2, p_xb, PP, 1, 0);

    // GRU1
    gemm(p_xb, PP, p_mem, EE, g1_wih, g1_bih, p_gi, 3*HH, 0, 0);
    wfrag_prep<<<3072, 256>>>(g1_whh);
    hfrag_zero<<<64, 256>>>();
    gru_pass<<<GRU_NBLK, 256>>>(0, g1_bhh);

    // attention linear + GRU2
    gemm(p_h1, HH, p_mem, EE, att_w, att_b, p_d2, HH, 0, 0);
    gemm(p_d2, HH, nullptr, 0, g2_wih, g2_bih, p_gi, 3*HH, 0, 0);
    wfrag_prep<<<3072, 256>>>(g2_whh);
    hfrag_zero<<<64, 256>>>();
    gru_pass<<<GRU_NBLK, 256>>>(1, g2_bhh);

    // r2 = h2 + d2
    add_kernel<<<8192, 256>>>(p_h2, p_d2, p_r2, (size_t)RR*HH);

    // GRU3
    gemm(p_r2, HH, nullptr, 0, g3_wih, g3_bih, p_gi, 3*HH, 0, 0);
    wfrag_prep<<<3072, 256>>>(g3_whh);
    hfrag_zero<<<64, 256>>>();
    gru_pass<<<GRU_NBLK, 256>>>(2, g3_bhh);

    // r3 = h3 + r2
    add_kernel<<<8192, 256>>>(p_h3, p_r2, p_d2, (size_t)RR*HH);

    // projection into [B,T,160]
    gemm(p_d2, HH, p_mem, EE, proj_w, proj_b, out, MMI*2, 0, 1);
}

// round 10
// speedup vs baseline: 3.1529x; 1.2811x over previous
#include <cuda_runtime.h>
#include <cuda_bf16.h>
#include <math.h>
#include <stdint.h>

#define BB   64
#define TMEL 2000
#define EE   512
#define MMI  80
#define PP   256
#define HH   1024
#define TD   1000
#define RR   (TD*BB)

#define GRU_NBLK 128

// ---------------- static device scratch (allocation-free rule) ----------------
__device__ float g_di [(size_t)RR*MMI];
__device__ float g_mem[(size_t)RR*EE];
__device__ float g_xa [(size_t)RR*PP];
__device__ float g_xb [(size_t)RR*PP];
__device__ float g_gi [(size_t)RR*3*HH];
__device__ float g_h1 [(size_t)RR*HH];
__device__ float g_h2 [(size_t)RR*HH];
__device__ float g_h3 [(size_t)RR*HH];
__device__ float g_d2 [(size_t)RR*HH];
__device__ float g_r2 [(size_t)RR*HH];

// mma-fragment-packed recurrent weights: [c(128)][w(8)][q(8)][nt(3)][lane(32)]
__device__ __align__(16) uint4 g_wfrag[(size_t)128*8*8*3*32];
// mma-A-fragment-packed h (hi+lo), ping-pong
__device__ __align__(16) uint4 g_hfrag[(size_t)2*4*64*64];

__device__ unsigned g_barcnt;
__device__ unsigned g_bargen;

// ---------------- prep kernels ----------------
__global__ void pool_kernel(const float* __restrict__ memorys)
{
    size_t total = (size_t)RR * EE;
    for (size_t i = (size_t)blockIdx.x*blockDim.x + threadIdx.x; i < total;
         i += (size_t)gridDim.x*blockDim.x) {
        int e = (int)(i % EE);
        int tb = (int)(i / EE);
        int b = tb & (BB-1);
        int t = tb >> 6;
        const float* src = memorys + ((size_t)b*TMEL + 2*t)*EE + e;
        g_mem[i] = 0.5f*(src[0] + src[EE]);
    }
}

__global__ void di_kernel(const float* __restrict__ dec)
{
    size_t total = (size_t)RR * MMI;
    for (size_t i = (size_t)blockIdx.x*blockDim.x + threadIdx.x; i < total;
         i += (size_t)gridDim.x*blockDim.x) {
        int m = (int)(i % MMI);
        int tb = (int)(i / MMI);
        int b = tb & (BB-1);
        int t = tb >> 6;
        g_di[i] = (t == 0) ? 0.0f : dec[((size_t)b*TMEL + (2*t-1))*MMI + m];
    }
}

__global__ void add_kernel(const float* __restrict__ a, const float* __restrict__ b,
                           float* __restrict__ c, size_t n)
{
    for (size_t i = (size_t)blockIdx.x*blockDim.x + threadIdx.x; i < n;
         i += (size_t)gridDim.x*blockDim.x)
        c[i] = a[i] + b[i];
}

__device__ __forceinline__ uint32_t pack_bf2(float lo, float hi)
{
    __nv_bfloat162 t = __floats2bfloat162_rn(lo, hi);   // .x in low 16 bits
    return *(uint32_t*)&t;
}

// pack whh into per-lane B fragments (bf16 hi/lo split)
__global__ void wfrag_prep(const float* __restrict__ whh)
{
    size_t idx = (size_t)blockIdx.x*blockDim.x + threadIdx.x;
    if (idx >= (size_t)128*8*8*3*32) return;
    int lane = (int)(idx & 31);
    size_t r1 = idx >> 5;
    int nt = (int)(r1 % 3);
    size_t r2 = r1 / 3;
    int q = (int)(r2 & 7);
    int w = (int)((r2 >> 3) & 7);
    int c = (int)(r2 >> 6);
    int gid = lane >> 2, tig = lane & 3;
    const float* wp = whh + (size_t)(nt*HH + c*8 + gid)*HH + w*128 + q*16;
    float v0 = wp[2*tig], v1 = wp[2*tig+1], v2 = wp[2*tig+8], v3 = wp[2*tig+9];
    float h0 = __bfloat162float(__float2bfloat16(v0));
    float h1 = __bfloat162float(__float2bfloat16(v1));
    float h2 = __bfloat162float(__float2bfloat16(v2));
    float h3 = __bfloat162float(__float2bfloat16(v3));
    uint4 o;
    o.x = pack_bf2(v0, v1);
    o.y = pack_bf2(v2, v3);
    o.z = pack_bf2(v0 - h0, v1 - h1);
    o.w = pack_bf2(v2 - h2, v3 - h3);
    g_wfrag[idx] = o;
}

__global__ void hfrag_zero()
{
    int i = blockIdx.x*blockDim.x + threadIdx.x;
    if (i < 4*64*64) g_hfrag[i] = make_uint4(0u,0u,0u,0u);
}

// ---------------- mma primitives ----------------
__device__ __forceinline__ void mma16816(float* c,
    uint32_t a0, uint32_t a1, uint32_t a2, uint32_t a3,
    uint32_t b0, uint32_t b1)
{
    asm volatile(
        "mma.sync.aligned.m16n8k16.row.col.f32.bf16.bf16.f32 "
        "{%0,%1,%2,%3}, {%4,%5,%6,%7}, {%8,%9}, {%0,%1,%2,%3};"
        : "+f"(c[0]), "+f"(c[1]), "+f"(c[2]), "+f"(c[3])
        : "r"(a0), "r"(a1), "r"(a2), "r"(a3), "r"(b0), "r"(b1));
}

// ---------------- tensor-core batch GEMM ----------------
// C[RR,N] = concat(A1[RR,K1], A2[RR,K2]) @ W[N,K]^T + bias, bf16 3-term split.
// Tile 128x128x32, 8 warps as 4(m) x 2(n), each warp 32x64 via m16n8k16.
#define GP 36   // smem pitch in bf16

__global__ __launch_bounds__(256)
void gemm_mma(const float* __restrict__ A1, int K1,
              const float* __restrict__ A2, int K2,
              const float* __restrict__ W,  const float* __restrict__ bias,
              float* __restrict__ C, int N, int doRelu, int outBT)
{
    __shared__ __nv_bfloat16 sAhi[128*GP], sAlo[128*GP];
    __shared__ __nv_bfloat16 sWhi[128*GP], sWlo[128*GP];

    const int K   = K1 + K2;
    const int Kce = (K + 31) & ~31;
    const int tid = threadIdx.x;
    const int lane = tid & 31, wid = tid >> 5;
    const int wm = wid >> 1, wn = wid & 1;       // 4 x 2 warp grid
    const int g = lane >> 2, tg = lane & 3;
    const int row0 = blockIdx.y * 128;
    const int n0   = blockIdx.x * 128;

    const int srow = tid >> 1;                   // staging row 0..127
    const int scol = (tid & 1) * 16;             // staging col base

    float acc[2][8][4];
#pragma unroll
    for (int mt = 0; mt < 2; mt++)
#pragma unroll
        for (int nt = 0; nt < 8; nt++)
#pragma unroll
            for (int r = 0; r < 4; r++) acc[mt][nt][r] = 0.0f;

    float4 pa[4], pw[4];
    // prefetch chunk 0
    {
        const int kc = 0;
#pragma unroll
        for (int f = 0; f < 4; f++) {
            int gc = kc + scol + f*4;
            float4 v = make_float4(0.f,0.f,0.f,0.f);
            if (gc < K) {
                if (gc < K1) v = *(const float4*)(A1 + (size_t)(row0+srow)*K1 + gc);
                else         v = *(const float4*)(A2 + (size_t)(row0+srow)*K2 + (gc-K1));
            }
            pa[f] = v;
            float4 wv = make_float4(0.f,0.f,0.f,0.f);
            int nr = n0 + srow;
            if (gc < K && nr < N) wv = *(const float4*)(W + (size_t)nr*K + gc);
            pw[f] = wv;
        }
    }

    for (int kc = 0; kc < Kce; kc += 32) {
        // stage: split fp32 -> bf16 hi/lo planes
        {
            float va[16], vw[16];
#pragma unroll
            for (int f = 0; f < 4; f++) {
                va[f*4+0]=pa[f].x; va[f*4+1]=pa[f].y; va[f*4+2]=pa[f].z; va[f*4+3]=pa[f].w;
                vw[f*4+0]=pw[f].x; vw[f*4+1]=pw[f].y; vw[f*4+2]=pw[f].z; vw[f*4+3]=pw[f].w;
            }
            int sb = srow*GP + scol;
#pragma unroll
            for (int j = 0; j < 8; j++) {
                float x0 = va[2*j], x1 = va[2*j+1];
                float h0 = __bfloat162float(__float2bfloat16(x0));
                float h1 = __bfloat162float(__float2bfloat16(x1));
                *(uint32_t*)&sAhi[sb + 2*j] = pack_bf2(x0, x1);
                *(uint32_t*)&sAlo[sb + 2*j] = pack_bf2(x0 - h0, x1 - h1);
                float y0 = vw[2*j], y1 = vw[2*j+1];
                float g0 = __bfloat162float(__float2bfloat16(y0));
                float g1 = __bfloat162float(__float2bfloat16(y1));
                *(uint32_t*)&sWhi[sb + 2*j] = pack_bf2(y0, y1);
                *(uint32_t*)&sWlo[sb + 2*j] = pack_bf2(y0 - g0, y1 - g1);
            }
        }
        __syncthreads();

        // prefetch next chunk
        if (kc + 32 < Kce) {
            const int kn = kc + 32;
#pragma unroll
            for (int f = 0; f < 4; f++) {
                int gc = kn + scol + f*4;
                float4 v = make_float4(0.f,0.f,0.f,0.f);
                if (gc < K) {
                    if (gc < K1) v = *(const float4*)(A1 + (size_t)(row0+srow)*K1 + gc);
                    else         v = *(const float4*)(A2 + (size_t)(row0+srow)*K2 + (gc-K1));
                }
                pa[f] = v;
                float4 wv = make_float4(0.f,0.f,0.f,0.f);
                int nr = n0 + srow;
                if (gc < K && nr < N) wv = *(const float4*)(W + (size_t)nr*K + gc);
                pw[f] = wv;
            }
        }

        // compute: 2 k16 steps
#pragma unroll
        for (int ks = 0; ks < 2; ks++) {
            uint32_t ah[2][4], al[2][4];
#pragma unroll
            for (int mt = 0; mt < 2; mt++) {
                int ra = (wm*32 + mt*16 + g)*GP + ks*16 + tg*2;
                ah[mt][0] = *(uint32_t*)&sAhi[ra];
                ah[mt][1] = *(uint32_t*)&sAhi[ra + 8*GP];
                ah[mt][2] = *(uint32_t*)&sAhi[ra + 8];
                ah[mt][3] = *(uint32_t*)&sAhi[ra + 8*GP + 8];
                al[mt][0] = *(uint32_t*)&sAlo[ra];
                al[mt][1] = *(uint32_t*)&sAlo[ra + 8*GP];
                al[mt][2] = *(uint32_t*)&sAlo[ra + 8];
                al[mt][3] = *(uint32_t*)&sAlo[ra + 8*GP + 8];
            }
#pragma unroll
            for (int nt = 0; nt < 8; nt++) {
                int rb = (wn*64 + nt*8 + g)*GP + ks*16 + tg*2;
                uint32_t bh0 = *(uint32_t*)&sWhi[rb];
                uint32_t bh1 = *(uint32_t*)&sWhi[rb + 8];
                uint32_t bl0 = *(uint32_t*)&sWlo[rb];
                uint32_t bl1 = *(uint32_t*)&sWlo[rb + 8];
#pragma unroll
                for (int mt = 0; mt < 2; mt++) {
                    mma16816(acc[mt][nt], ah[mt][0], ah[mt][1], ah[mt][2], ah[mt][3], bh0, bh1);
                    mma16816(acc[mt][nt], ah[mt][0], ah[mt][1], ah[mt][2], ah[mt][3], bl0, bl1);
                    mma16816(acc[mt][nt], al[mt][0], al[mt][1], al[mt][2], al[mt][3], bh0, bh1);
                }
            }
        }
        __syncthreads();
    }

    // epilogue
#pragma unroll
    for (int mt = 0; mt < 2; mt++) {
        int mrow0 = row0 + wm*32 + mt*16 + g;
#pragma unroll
        for (int nt = 0; nt < 8; nt++) {
            int col = n0 + wn*64 + nt*8 + tg*2;
#pragma unroll
            for (int r = 0; r < 4; r++) {
                int m = mrow0 + (r >> 1)*8;
                int n = col + (r & 1);
                if (n < N) {
                    float v = acc[mt][nt][r] + bias[n];
                    if (doRelu) v = fmaxf(v, 0.0f);
                    if (outBT) {
                        int t = m >> 6, b = m & (BB-1);
                        C[((size_t)b*TD + t)*N + n] = v;
                    } else {
                        C[(size_t)m*N + n] = v;
                    }
                }
            }
        }
    }
}

// ---------------- persistent mma.sync GRU recurrence (unchanged, verified) ----------------
__device__ __forceinline__ float sigmoidf(float x) { return 1.0f/(1.0f + expf(-x)); }

__device__ __forceinline__ void grid_barrier()
{
    __threadfence();
    __syncthreads();
    if (threadIdx.x == 0) {
        unsigned g = *(volatile unsigned*)&g_bargen;
        unsigned old = atomicAdd(&g_barcnt, 1u);
        if (old == GRU_NBLK - 1u) {
            atomicExch(&g_barcnt, 0u);
            __threadfence();
            atomicAdd(&g_bargen, 1u);
        } else {
            while (*(volatile unsigned*)&g_bargen == g) { }
        }
        __threadfence();
    }
    __syncthreads();
}

__global__ __launch_bounds__(256, 1)
void gru_pass(int pass, const float* __restrict__ bhh)
{
    float* hall = (pass == 0) ? g_h1 : (pass == 1) ? g_h2 : g_h3;
    __shared__ float sred[12288];
    const int tid = threadIdx.x, wid = tid >> 5, lane = tid & 31;
    const int c = blockIdx.x;
    const uint4* wbase = g_wfrag + ((size_t)(c*8 + wid)*8)*3*32;

    for (int t = 0; t < TD; t++) {
        const int par = t & 1;
        const uint4* hbase = g_hfrag + (size_t)par*4*64*64;

        float acc[4][3][4];
#pragma unroll
        for (int m = 0; m < 4; m++)
#pragma unroll
            for (int nt = 0; nt < 3; nt++)
#pragma unroll
                for (int r = 0; r < 4; r++) acc[m][nt][r] = 0.0f;

#pragma unroll 2
        for (int q = 0; q < 8; q++) {
            const int s = wid*8 + q;
            uint4 ah[4], al[4];
#pragma unroll
            for (int m = 0; m < 4; m++) {
                const uint4* p = hbase + ((size_t)m*64 + s)*64 + lane*2;
                ah[m] = p[0];
                al[m] = p[1];
            }
            uint4 bw[3];
#pragma unroll
            for (int nt = 0; nt < 3; nt++)
                bw[nt] = wbase[(q*3 + nt)*32 + lane];
#pragma unroll
            for (int m = 0; m < 4; m++)
#pragma unroll
                for (int nt = 0; nt < 3; nt++) {
                    mma16816(acc[m][nt], ah[m].x, ah[m].y, ah[m].z, ah[m].w, bw[nt].x, bw[nt].y);
                    mma16816(acc[m][nt], ah[m].x, ah[m].y, ah[m].z, ah[m].w, bw[nt].z, bw[nt].w);
                    mma16816(acc[m][nt], al[m].x, al[m].y, al[m].z, al[m].w, bw[nt].x, bw[nt].y);
                }
        }
#pragma unroll
        for (int m = 0; m < 4; m++)
#pragma unroll
            for (int nt = 0; nt < 3; nt++)
#pragma unroll
                for (int r = 0; r < 4; r++)
                    sred[(((wid*4 + m)*3 + nt)*4 + r)*32 + lane] = acc[m][nt][r];
        __syncthreads();

        const int par2 = (t + 1) & 1;
        for (int o = tid; o < 512; o += 256) {
            int b = o >> 3, j = o & 7;
            int jg = c*8 + j;
            int m = b >> 4;
            int rowhi = (b >> 3) & 1;
            int lo_ = (b & 7)*4 + (j >> 1);
            int rc = rowhi*2 + (j & 1);
            float gsum[3];
#pragma unroll
            for (int nt = 0; nt < 3; nt++) {
                float s_ = 0.0f;
#pragma unroll
                for (int w = 0; w < 8; w++)
                    s_ += sred[(((w*4 + m)*3 + nt)*4 + rc)*32 + lo_];
                gsum[nt] = s_;
            }
            const float* gib = g_gi + ((size_t)t*BB + b)*3*HH;
            float rr = sigmoidf(gib[jg]        + gsum[0] + bhh[jg]);
            float zz = sigmoidf(gib[HH + jg]   + gsum[1] + bhh[HH + jg]);
            float nn = tanhf   (gib[2*HH + jg] + rr*(gsum[2] + bhh[2*HH + jg]));
            float hp = (t > 0) ? hall[((size_t)(t-1)*BB + b)*HH + jg] : 0.0f;
            float h  = (1.0f - zz)*nn + zz*hp;
            hall[((size_t)t*BB + b)*HH + jg] = h;

            __nv_bfloat16 hhi = __float2bfloat16(h);
            __nv_bfloat16 hlo = __float2bfloat16(h - __bfloat162float(hhi));
            int s = jg >> 4;
            int colhi = c & 1;
            int reg = rowhi + 2*colhi;
            uint8_t* base = (uint8_t*)g_hfrag
                + (((size_t)par2*4 + m)*64 + s)*1024 + lo_*32;
            *(__nv_bfloat16*)(base + reg*4 + (j & 1)*2)      = hhi;
            *(__nv_bfloat16*)(base + 16 + reg*4 + (j & 1)*2) = hlo;
        }
        grid_barrier();
    }
}

// ---------------- host orchestration ----------------
extern "C" void kernel_launch(void* const* d_in, const int* in_sizes, int n_in,
                              void* d_out, int out_size)
{
    const float* memorys = (const float*)d_in[0];
    const float* dec     = (const float*)d_in[1];
    const float* pre_w1 = (const float*)d_in[3];
    const float* pre_b1 = (const float*)d_in[4];
    const float* pre_w2 = (const float*)d_in[5];
    const float* pre_b2 = (const float*)d_in[6];
    const float* g1_wih = (const float*)d_in[7];
    const float* g1_whh = (const float*)d_in[8];
    const float* g1_bih = (const float*)d_in[9];
    const float* g1_bhh = (const float*)d_in[10];
    const float* att_w  = (const float*)d_in[11];
    const float* att_b  = (const float*)d_in[12];
    const float* g2_wih = (const float*)d_in[13];
    const float* g2_whh = (const float*)d_in[14];
    const float* g2_bih = (const float*)d_in[15];
    const float* g2_bhh = (const float*)d_in[16];
    const float* g3_wih = (const float*)d_in[17];
    const float* g3_whh = (const float*)d_in[18];
    const float* g3_bih = (const float*)d_in[19];
    const float* g3_bhh = (const float*)d_in[20];
    const float* proj_w = (const float*)d_in[21];
    const float* proj_b = (const float*)d_in[22];
    float* out = (float*)d_out;

    float *p_di,*p_mem,*p_xa,*p_xb,*p_gi,*p_h1,*p_h2,*p_h3,*p_d2,*p_r2;
    cudaGetSymbolAddress((void**)&p_di,  g_di);
    cudaGetSymbolAddress((void**)&p_mem, g_mem);
    cudaGetSymbolAddress((void**)&p_xa,  g_xa);
    cudaGetSymbolAddress((void**)&p_xb,  g_xb);
    cudaGetSymbolAddress((void**)&p_gi,  g_gi);
    cudaGetSymbolAddress((void**)&p_h1,  g_h1);
    cudaGetSymbolAddress((void**)&p_h2,  g_h2);
    cudaGetSymbolAddress((void**)&p_h3,  g_h3);
    cudaGetSymbolAddress((void**)&p_d2,  g_d2);
    cudaGetSymbolAddress((void**)&p_r2,  g_r2);

    pool_kernel<<<4096, 256>>>(memorys);
    di_kernel  <<<4096, 256>>>(dec);

    auto gemm = [&](const float* A1, int K1, const float* A2, int K2,
                    const float* W, const float* b, float* C, int N,
                    int relu, int bt) {
        dim3 grid((N + 127)/128, RR/128);
        gemm_mma<<<grid, 256>>>(A1, K1, A2, K2, W, b, C, N, relu, bt);
    };

    // prenet
    gemm(p_di, MMI, nullptr, 0, pre_w1, pre_b1, p_xa, PP, 1, 0);
    gemm(p_xa, PP,  nullptr, 0, pre_w2, pre_b2, p_xb, PP, 1, 0);

    // GRU1
    gemm(p_xb, PP, p_mem, EE, g1_wih, g1_bih, p_gi, 3*HH, 0, 0);
    wfrag_prep<<<3072, 256>>>(g1_whh);
    hfrag_zero<<<64, 256>>>();
    gru_pass<<<GRU_NBLK, 256>>>(0, g1_bhh);

    // attention linear + GRU2
    gemm(p_h1, HH, p_mem, EE, att_w, att_b, p_d2, HH, 0, 0);
    gemm(p_d2, HH, nullptr, 0, g2_wih, g2_bih, p_gi, 3*HH, 0, 0);
    wfrag_prep<<<3072, 256>>>(g2_whh);
    hfrag_zero<<<64, 256>>>();
    gru_pass<<<GRU_NBLK, 256>>>(1, g2_bhh);

    // r2 = h2 + d2
    add_kernel<<<8192, 256>>>(p_h2, p_d2, p_r2, (size_t)RR*HH);

    // GRU3
    gemm(p_r2, HH, nullptr, 0, g3_wih, g3_bih, p_gi, 3*HH, 0, 0);
    wfrag_prep<<<3072, 256>>>(g3_whh);
    hfrag_zero<<<64, 256>>>();
    gru_pass<<<GRU_NBLK, 256>>>(2, g3_bhh);

    // r3 = h3 + r2
    add_kernel<<<8192, 256>>>(p_h3, p_r2, p_d2, (size_t)RR*HH);

    // projection into [B,T,160]
    gemm(p_d2, HH, p_mem, EE, proj_w, proj_b, out, MMI*2, 0, 1);
}

// round 11
// speedup vs baseline: 3.6475x; 1.1569x over previous
#include <cuda_runtime.h>
#include <cuda_bf16.h>
#include <math.h>
#include <stdint.h>

#define BB   64
#define TMEL 2000
#define EE   512
#define MMI  80
#define PP   256
#define HH   1024
#define TD   1000
#define RR   (TD*BB)

#define GRU_NBLK 128

// ---------------- static device scratch (allocation-free rule) ----------------
__device__ float g_di [(size_t)RR*MMI];
__device__ float g_mem[(size_t)RR*EE];
__device__ float g_xa [(size_t)RR*PP];
__device__ float g_xb [(size_t)RR*PP];
__device__ float g_gi [(size_t)RR*3*HH];
__device__ float g_h1 [(size_t)RR*HH];
__device__ float g_h2 [(size_t)RR*HH];
__device__ float g_h3 [(size_t)RR*HH];
__device__ float g_d2 [(size_t)RR*HH];
__device__ float g_r2 [(size_t)RR*HH];

// bf16 hi/lo planes for GEMM operands (pre-split, concat + padding done here)
__device__ __align__(16) __nv_bfloat16 g_Ahi[(size_t)RR*1536];
__device__ __align__(16) __nv_bfloat16 g_Alo[(size_t)RR*1536];
__device__ __align__(16) __nv_bfloat16 g_Whi[(size_t)3072*1536];
__device__ __align__(16) __nv_bfloat16 g_Wlo[(size_t)3072*1536];

// mma-fragment-packed recurrent weights + h ping-pong (verified)
__device__ __align__(16) uint4 g_wfrag[(size_t)128*8*8*3*32];
__device__ __align__(16) uint4 g_hfrag[(size_t)2*4*64*64];

__device__ unsigned g_barcnt;
__device__ unsigned g_bargen;

// ---------------- prep kernels ----------------
__global__ void pool_kernel(const float* __restrict__ memorys)
{
    size_t total = (size_t)RR * EE;
    for (size_t i = (size_t)blockIdx.x*blockDim.x + threadIdx.x; i < total;
         i += (size_t)gridDim.x*blockDim.x) {
        int e = (int)(i % EE);
        int tb = (int)(i / EE);
        int b = tb & (BB-1);
        int t = tb >> 6;
        const float* src = memorys + ((size_t)b*TMEL + 2*t)*EE + e;
        g_mem[i] = 0.5f*(src[0] + src[EE]);
    }
}

__global__ void di_kernel(const float* __restrict__ dec)
{
    size_t total = (size_t)RR * MMI;
    for (size_t i = (size_t)blockIdx.x*blockDim.x + threadIdx.x; i < total;
         i += (size_t)gridDim.x*blockDim.x) {
        int m = (int)(i % MMI);
        int tb = (int)(i / MMI);
        int b = tb & (BB-1);
        int t = tb >> 6;
        g_di[i] = (t == 0) ? 0.0f : dec[((size_t)b*TMEL + (2*t-1))*MMI + m];
    }
}

__global__ void add_kernel(const float* __restrict__ a, const float* __restrict__ b,
                           float* __restrict__ c, size_t n)
{
    for (size_t i = (size_t)blockIdx.x*blockDim.x + threadIdx.x; i < n;
         i += (size_t)gridDim.x*blockDim.x)
        c[i] = a[i] + b[i];
}

__device__ __forceinline__ uint32_t pack_bf2(float lo, float hi)
{
    __nv_bfloat162 t = __floats2bfloat162_rn(lo, hi);
    return *(uint32_t*)&t;
}

// split concat(A1,A2) -> bf16 hi/lo planes [RR][Kce], zero-padded to Kce
__global__ void splitA(const float* __restrict__ A1, int K1,
                       const float* __restrict__ A2, int K2, int Kce)
{
    size_t total = (size_t)RR * Kce;
    for (size_t i = (size_t)blockIdx.x*blockDim.x + threadIdx.x; i < total;
         i += (size_t)gridDim.x*blockDim.x) {
        int k = (int)(i % Kce);
        size_t r = i / Kce;
        float v = 0.0f;
        if (k < K1)           v = A1[r*K1 + k];
        else if (k < K1 + K2) v = A2[r*K2 + (k - K1)];
        __nv_bfloat16 hi = __float2bfloat16(v);
        g_Ahi[i] = hi;
        g_Alo[i] = __float2bfloat16(v - __bfloat162float(hi));
    }
}

// split W[N][K] -> bf16 hi/lo planes [Nce][Kce], zero-padded
__global__ void splitW(const float* __restrict__ W, int N, int K, int Nce, int Kce)
{
    size_t total = (size_t)Nce * Kce;
    for (size_t i = (size_t)blockIdx.x*blockDim.x + threadIdx.x; i < total;
         i += (size_t)gridDim.x*blockDim.x) {
        int k = (int)(i % Kce);
        int n = (int)(i / Kce);
        float v = (n < N && k < K) ? W[(size_t)n*K + k] : 0.0f;
        __nv_bfloat16 hi = __float2bfloat16(v);
        g_Whi[i] = hi;
        g_Wlo[i] = __float2bfloat16(v - __bfloat162float(hi));
    }
}

// pack whh into per-lane B fragments (verified)
__global__ void wfrag_prep(const float* __restrict__ whh)
{
    size_t idx = (size_t)blockIdx.x*blockDim.x + threadIdx.x;
    if (idx >= (size_t)128*8*8*3*32) return;
    int lane = (int)(idx & 31);
    size_t r1 = idx >> 5;
    int nt = (int)(r1 % 3);
    size_t r2 = r1 / 3;
    int q = (int)(r2 & 7);
    int w = (int)((r2 >> 3) & 7);
    int c = (int)(r2 >> 6);
    int gid = lane >> 2, tig = lane & 3;
    const float* wp = whh + (size_t)(nt*HH + c*8 + gid)*HH + w*128 + q*16;
    float v0 = wp[2*tig], v1 = wp[2*tig+1], v2 = wp[2*tig+8], v3 = wp[2*tig+9];
    float h0 = __bfloat162float(__float2bfloat16(v0));
    float h1 = __bfloat162float(__float2bfloat16(v1));
    float h2 = __bfloat162float(__float2bfloat16(v2));
    float h3 = __bfloat162float(__float2bfloat16(v3));
    uint4 o;
    o.x = pack_bf2(v0, v1);
    o.y = pack_bf2(v2, v3);
    o.z = pack_bf2(v0 - h0, v1 - h1);
    o.w = pack_bf2(v2 - h2, v3 - h3);
    g_wfrag[idx] = o;
}

__global__ void hfrag_zero()
{
    int i = blockIdx.x*blockDim.x + threadIdx.x;
    if (i < 4*64*64) g_hfrag[i] = make_uint4(0u,0u,0u,0u);
}

// ---------------- mma primitives ----------------
__device__ __forceinline__ void mma16816(float* c,
    uint32_t a0, uint32_t a1, uint32_t a2, uint32_t a3,
    uint32_t b0, uint32_t b1)
{
    asm volatile(
        "mma.sync.aligned.m16n8k16.row.col.f32.bf16.bf16.f32 "
        "{%0,%1,%2,%3}, {%4,%5,%6,%7}, {%8,%9}, {%0,%1,%2,%3};"
        : "+f"(c[0]), "+f"(c[1]), "+f"(c[2]), "+f"(c[3])
        : "r"(a0), "r"(a1), "r"(a2), "r"(a3), "r"(b0), "r"(b1));
}

__device__ __forceinline__ uint32_t smem_u32(const void* p) {
    uint32_t a;
    asm("{ .reg .u64 t; cvta.to.shared.u64 t, %1; cvt.u32.u64 %0, t; }" : "=r"(a) : "l"(p));
    return a;
}
#define CP_ASYNC16(dst, src) \
    asm volatile("cp.async.cg.shared.global [%0], [%1], 16;" :: "r"(dst), "l"(src) : "memory")
#define CP_COMMIT() asm volatile("cp.async.commit_group;" ::: "memory")
#define CP_WAIT(n)  asm volatile("cp.async.wait_group %0;" :: "n"(n) : "memory")

// ---------------- tensor-core batch GEMM, cp.async 2-stage, pre-split planes ----------------
// tile 128x128x32; 8 warps 4(m)x2(n); pitch 40 bf16 (80 B, 16B-aligned rows, conflict-free)
#define GP2      40
#define PLANE_B  (128*GP2*2)          // 10240 B per plane
#define STAGE2_B (4*PLANE_B)          // 40960 B per stage
#define GEMM2_SMEM (2*STAGE2_B)       // 81920 B

__global__ __launch_bounds__(256, 2)
void gemm_mma2(int KA, int N, const float* __restrict__ bias,
               float* __restrict__ C, int doRelu, int outBT)
{
    extern __shared__ char dynsm[];
    const int tid = threadIdx.x;
    const int lane = tid & 31, wid = tid >> 5;
    const int wm = wid >> 1, wn = wid & 1;
    const int g = lane >> 2, tg = lane & 3;
    const int row0 = blockIdx.y * 128;
    const int n0   = blockIdx.x * 128;
    const int nch  = KA >> 5;

    // issue one stage's copies: 2048 x 16B, 8 per thread
    auto issue_stage = [&](int st, int ci) {
        const int kc = ci * 32;
        uint32_t sbase = smem_u32(dynsm) + st*STAGE2_B;
#pragma unroll
        for (int u = 0; u < 8; u++) {
            int e = tid + u*256;
            int plane = e >> 9;            // 0:Ahi 1:Alo 2:Whi 3:Wlo
            int r  = (e & 511) >> 2;
            int cb = e & 3;
            const __nv_bfloat16* src;
            if (plane == 0)      src = g_Ahi + (size_t)(row0 + r)*KA + kc + cb*8;
            else if (plane == 1) src = g_Alo + (size_t)(row0 + r)*KA + kc + cb*8;
            else if (plane == 2) src = g_Whi + (size_t)(n0 + r)*KA + kc + cb*8;
            else                 src = g_Wlo + (size_t)(n0 + r)*KA + kc + cb*8;
            uint32_t dst = sbase + plane*PLANE_B + r*(GP2*2) + cb*16;
            CP_ASYNC16(dst, src);
        }
        CP_COMMIT();
    };

    float acc[2][8][4];
#pragma unroll
    for (int mt = 0; mt < 2; mt++)
#pragma unroll
        for (int nt = 0; nt < 8; nt++)
#pragma unroll
            for (int r = 0; r < 4; r++) acc[mt][nt][r] = 0.0f;

    issue_stage(0, 0);
    if (nch > 1) issue_stage(1, 1);

    for (int i = 0; i < nch; i++) {
        if (i + 1 < nch) { CP_WAIT(1); } else { CP_WAIT(0); }
        __syncthreads();

        const __nv_bfloat16* sAhi = (const __nv_bfloat16*)(dynsm + (i&1)*STAGE2_B);
        const __nv_bfloat16* sAlo = sAhi + 128*GP2;
        const __nv_bfloat16* sWhi = sAlo + 128*GP2;
        const __nv_bfloat16* sWlo = sWhi + 128*GP2;

#pragma unroll
        for (int ks = 0; ks < 2; ks++) {
            uint32_t ah[2][4], al[2][4];
#pragma unroll
            for (int mt = 0; mt < 2; mt++) {
                int ra = (wm*32 + mt*16 + g)*GP2 + ks*16 + tg*2;
                ah[mt][0] = *(const uint32_t*)&sAhi[ra];
                ah[mt][1] = *(const uint32_t*)&sAhi[ra + 8*GP2];
                ah[mt][2] = *(const uint32_t*)&sAhi[ra + 8];
                ah[mt][3] = *(const uint32_t*)&sAhi[ra + 8*GP2 + 8];
                al[mt][0] = *(const uint32_t*)&sAlo[ra];
                al[mt][1] = *(const uint32_t*)&sAlo[ra + 8*GP2];
                al[mt][2] = *(const uint32_t*)&sAlo[ra + 8];
                al[mt][3] = *(const uint32_t*)&sAlo[ra + 8*GP2 + 8];
            }
#pragma unroll
            for (int nt = 0; nt < 8; nt++) {
                int rb = (wn*64 + nt*8 + g)*GP2 + ks*16 + tg*2;
                uint32_t bh0 = *(const uint32_t*)&sWhi[rb];
                uint32_t bh1 = *(const uint32_t*)&sWhi[rb + 8];
                uint32_t bl0 = *(const uint32_t*)&sWlo[rb];
                uint32_t bl1 = *(const uint32_t*)&sWlo[rb + 8];
#pragma unroll
                for (int mt = 0; mt < 2; mt++) {
                    mma16816(acc[mt][nt], ah[mt][0], ah[mt][1], ah[mt][2], ah[mt][3], bh0, bh1);
                    mma16816(acc[mt][nt], ah[mt][0], ah[mt][1], ah[mt][2], ah[mt][3], bl0, bl1);
                    mma16816(acc[mt][nt], al[mt][0], al[mt][1], al[mt][2], al[mt][3], bh0, bh1);
                }
            }
        }
        __syncthreads();
        if (i + 2 < nch) issue_stage(i & 1, i + 2);
    }

    // epilogue (verified mapping)
#pragma unroll
    for (int mt = 0; mt < 2; mt++) {
        int mrow0 = row0 + wm*32 + mt*16 + g;
#pragma unroll
        for (int nt = 0; nt < 8; nt++) {
            int col = n0 + wn*64 + nt*8 + tg*2;
#pragma unroll
            for (int r = 0; r < 4; r++) {
                int m = mrow0 + (r >> 1)*8;
                int n = col + (r & 1);
                if (n < N) {
                    float v = acc[mt][nt][r] + bias[n];
                    if (doRelu) v = fmaxf(v, 0.0f);
                    if (outBT) {
                        int t = m >> 6, b = m & (BB-1);
                        C[((size_t)b*TD + t)*N + n] = v;
                    } else {
                        C[(size_t)m*N + n] = v;
                    }
                }
            }
        }
    }
}

// ---------------- persistent mma.sync GRU recurrence (verified, unchanged) ----------------
__device__ __forceinline__ float sigmoidf(float x) { return 1.0f/(1.0f + expf(-x)); }

__device__ __forceinline__ void grid_barrier()
{
    __threadfence();
    __syncthreads();
    if (threadIdx.x == 0) {
        unsigned g = *(volatile unsigned*)&g_bargen;
        unsigned old = atomicAdd(&g_barcnt, 1u);
        if (old == GRU_NBLK - 1u) {
            atomicExch(&g_barcnt, 0u);
            __threadfence();
            atomicAdd(&g_bargen, 1u);
        } else {
            while (*(volatile unsigned*)&g_bargen == g) { }
        }
        __threadfence();
    }
    __syncthreads();
}

__global__ __launch_bounds__(256, 1)
void gru_pass(int pass, const float* __restrict__ bhh)
{
    float* hall = (pass == 0) ? g_h1 : (pass == 1) ? g_h2 : g_h3;
    __shared__ float sred[12288];
    const int tid = threadIdx.x, wid = tid >> 5, lane = tid & 31;
    const int c = blockIdx.x;
    const uint4* wbase = g_wfrag + ((size_t)(c*8 + wid)*8)*3*32;

    for (int t = 0; t < TD; t++) {
        const int par = t & 1;
        const uint4* hbase = g_hfrag + (size_t)par*4*64*64;

        float acc[4][3][4];
#pragma unroll
        for (int m = 0; m < 4; m++)
#pragma unroll
            for (int nt = 0; nt < 3; nt++)
#pragma unroll
                for (int r = 0; r < 4; r++) acc[m][nt][r] = 0.0f;

#pragma unroll 2
        for (int q = 0; q < 8; q++) {
            const int s = wid*8 + q;
            uint4 ah[4], al[4];
#pragma unroll
            for (int m = 0; m < 4; m++) {
                const uint4* p = hbase + ((size_t)m*64 + s)*64 + lane*2;
                ah[m] = p[0];
                al[m] = p[1];
            }
            uint4 bw[3];
#pragma unroll
            for (int nt = 0; nt < 3; nt++)
                bw[nt] = wbase[(q*3 + nt)*32 + lane];
#pragma unroll
            for (int m = 0; m < 4; m++)
#pragma unroll
                for (int nt = 0; nt < 3; nt++) {
                    mma16816(acc[m][nt], ah[m].x, ah[m].y, ah[m].z, ah[m].w, bw[nt].x, bw[nt].y);
                    mma16816(acc[m][nt], ah[m].x, ah[m].y, ah[m].z, ah[m].w, bw[nt].z, bw[nt].w);
                    mma16816(acc[m][nt], al[m].x, al[m].y, al[m].z, al[m].w, bw[nt].x, bw[nt].y);
                }
        }
#pragma unroll
        for (int m = 0; m < 4; m++)
#pragma unroll
            for (int nt = 0; nt < 3; nt++)
#pragma unroll
                for (int r = 0; r < 4; r++)
                    sred[(((wid*4 + m)*3 + nt)*4 + r)*32 + lane] = acc[m][nt][r];
        __syncthreads();

        const int par2 = (t + 1) & 1;
        for (int o = tid; o < 512; o += 256) {
            int b = o >> 3, j = o & 7;
            int jg = c*8 + j;
            int m = b >> 4;
            int rowhi = (b >> 3) & 1;
            int lo_ = (b & 7)*4 + (j >> 1);
            int rc = rowhi*2 + (j & 1);
            float gsum[3];
#pragma unroll
            for (int nt = 0; nt < 3; nt++) {
                float s_ = 0.0f;
#pragma unroll
                for (int w = 0; w < 8; w++)
                    s_ += sred[(((w*4 + m)*3 + nt)*4 + rc)*32 + lo_];
                gsum[nt] = s_;
            }
            const float* gib = g_gi + ((size_t)t*BB + b)*3*HH;
            float rr = sigmoidf(gib[jg]        + gsum[0] + bhh[jg]);
            float zz = sigmoidf(gib[HH + jg]   + gsum[1] + bhh[HH + jg]);
            float nn = tanhf   (gib[2*HH + jg] + rr*(gsum[2] + bhh[2*HH + jg]));
            float hp = (t > 0) ? hall[((size_t)(t-1)*BB + b)*HH + jg] : 0.0f;
            float h  = (1.0f - zz)*nn + zz*hp;
            hall[((size_t)t*BB + b)*HH + jg] = h;

            __nv_bfloat16 hhi = __float2bfloat16(h);
            __nv_bfloat16 hlo = __float2bfloat16(h - __bfloat162float(hhi));
            int s = jg >> 4;
            int colhi = c & 1;
            int reg = rowhi + 2*colhi;
            uint8_t* base = (uint8_t*)g_hfrag
                + (((size_t)par2*4 + m)*64 + s)*1024 + lo_*32;
            *(__nv_bfloat16*)(base + reg*4 + (j & 1)*2)      = hhi;
            *(__nv_bfloat16*)(base + 16 + reg*4 + (j & 1)*2) = hlo;
        }
        grid_barrier();
    }
}

// ---------------- host orchestration ----------------
extern "C" void kernel_launch(void* const* d_in, const int* in_sizes, int n_in,
                              void* d_out, int out_size)
{
    const float* memorys = (const float*)d_in[0];
    const float* dec     = (const float*)d_in[1];
    const float* pre_w1 = (const float*)d_in[3];
    const float* pre_b1 = (const float*)d_in[4];
    const float* pre_w2 = (const float*)d_in[5];
    const float* pre_b2 = (const float*)d_in[6];
    const float* g1_wih = (const float*)d_in[7];
    const float* g1_whh = (const float*)d_in[8];
    const float* g1_bih = (const float*)d_in[9];
    const float* g1_bhh = (const float*)d_in[10];
    const float* att_w  = (const float*)d_in[11];
    const float* att_b  = (const float*)d_in[12];
    const float* g2_wih = (const float*)d_in[13];
    const float* g2_whh = (const float*)d_in[14];
    const float* g2_bih = (const float*)d_in[15];
    const float* g2_bhh = (const float*)d_in[16];
    const float* g3_wih = (const float*)d_in[17];
    const float* g3_whh = (const float*)d_in[18];
    const float* g3_bih = (const float*)d_in[19];
    const float* g3_bhh = (const float*)d_in[20];
    const float* proj_w = (const float*)d_in[21];
    const float* proj_b = (const float*)d_in[22];
    float* out = (float*)d_out;

    float *p_di,*p_mem,*p_xa,*p_xb,*p_gi,*p_h1,*p_h2,*p_h3,*p_d2,*p_r2;
    cudaGetSymbolAddress((void**)&p_di,  g_di);
    cudaGetSymbolAddress((void**)&p_mem, g_mem);
    cudaGetSymbolAddress((void**)&p_xa,  g_xa);
    cudaGetSymbolAddress((void**)&p_xb,  g_xb);
    cudaGetSymbolAddress((void**)&p_gi,  g_gi);
    cudaGetSymbolAddress((void**)&p_h1,  g_h1);
    cudaGetSymbolAddress((void**)&p_h2,  g_h2);
    cudaGetSymbolAddress((void**)&p_h3,  g_h3);
    cudaGetSymbolAddress((void**)&p_d2,  g_d2);
    cudaGetSymbolAddress((void**)&p_r2,  g_r2);

    cudaFuncSetAttribute(gemm_mma2, cudaFuncAttributeMaxDynamicSharedMemorySize, GEMM2_SMEM);

    pool_kernel<<<4096, 256>>>(memorys);
    di_kernel  <<<4096, 256>>>(dec);

    // split + gemm wrapper: Kce/Nce padded to 32/128
    auto gemm = [&](const float* A1, int K1, const float* A2, int K2,
                    const float* W, const float* b, float* C, int N,
                    int relu, int bt) {
        int K = K1 + K2;
        int Kce = (K + 31) & ~31;
        int Nce = (N + 127) & ~127;
        splitA<<<8192, 256>>>(A1, K1, A2, K2, Kce);
        splitW<<<2048, 256>>>(W, N, K, Nce, Kce);
        dim3 grid(Nce/128, RR/128);
        gemm_mma2<<<grid, 256, GEMM2_SMEM>>>(Kce, N, b, C, relu, bt);
    };

    // prenet
    gemm(p_di, MMI, nullptr, 0, pre_w1, pre_b1, p_xa, PP, 1, 0);
    gemm(p_xa, PP,  nullptr, 0, pre_w2, pre_b2, p_xb, PP, 1, 0);

    // GRU1
    gemm(p_xb, PP, p_mem, EE, g1_wih, g1_bih, p_gi, 3*HH, 0, 0);
    wfrag_prep<<<3072, 256>>>(g1_whh);
    hfrag_zero<<<64, 256>>>();
    gru_pass<<<GRU_NBLK, 256>>>(0, g1_bhh);

    // attention linear + GRU2
    gemm(p_h1, HH, p_mem, EE, att_w, att_b, p_d2, HH, 0, 0);
    gemm(p_d2, HH, nullptr, 0, g2_wih, g2_bih, p_gi, 3*HH, 0, 0);
    wfrag_prep<<<3072, 256>>>(g2_whh);
    hfrag_zero<<<64, 256>>>();
    gru_pass<<<GRU_NBLK, 256>>>(1, g2_bhh);

    // r2 = h2 + d2
    add_kernel<<<8192, 256>>>(p_h2, p_d2, p_r2, (size_t)RR*HH);

    // GRU3
    gemm(p_r2, HH, nullptr, 0, g3_wih, g3_bih, p_gi, 3*HH, 0, 0);
    wfrag_prep<<<3072, 256>>>(g3_whh);
    hfrag_zero<<<64, 256>>>();
    gru_pass<<<GRU_NBLK, 256>>>(2, g3_bhh);

    // r3 = h3 + r2
    add_kernel<<<8192, 256>>>(p_h3, p_r2, p_d2, (size_t)RR*HH);

    // projection into [B,T,160]
    gemm(p_d2, HH, p_mem, EE, proj_w, proj_b, out, MMI*2, 0, 1);
}

// round 12
// speedup vs baseline: 4.2948x; 1.1775x over previous
#include <cuda_runtime.h>
#include <cuda_bf16.h>
#include <math.h>
#include <stdint.h>

#define BB   64
#define TMEL 2000
#define EE   512
#define MMI  80
#define PP   256
#define HH   1024
#define TD   1000
#define RR   (TD*BB)

#define GRU_NBLK 128
#define NRB      (RR/128)      // 500 row blocks

// ---------------- static device scratch (allocation-free rule) ----------------
__device__ float g_di [(size_t)RR*MMI];
__device__ float g_mem[(size_t)RR*EE];
__device__ float g_xa [(size_t)RR*PP];
__device__ float g_xb [(size_t)RR*PP];
__device__ float g_gi [(size_t)RR*3*HH];
__device__ float g_h1 [(size_t)RR*HH];
__device__ float g_h2 [(size_t)RR*HH];
__device__ float g_h3 [(size_t)RR*HH];
__device__ float g_d2 [(size_t)RR*HH];
__device__ float g_r2 [(size_t)RR*HH];

// fragment-packed GEMM operands
// A: [rb(500)][ci(<=48)][ (ks*8+mt)*32+lane ][2]  uint4 (hi, lo)   393 MB max
__device__ __align__(16) uint4 g_Afrag[(size_t)NRB*48*1024];
// W: [nb(<=24)][ci(<=48)][ (ks*16+ntile)*32+lane ] uint4 {bh0,bh1,bl0,bl1}  18.9 MB
__device__ __align__(16) uint4 g_Wfrag2[(size_t)24*48*1024];

// mma-fragment-packed recurrent weights + h ping-pong (verified)
__device__ __align__(16) uint4 g_wfrag[(size_t)128*8*8*3*32];
__device__ __align__(16) uint4 g_hfrag[(size_t)2*4*64*64];

__device__ unsigned g_barcnt;
__device__ unsigned g_bargen;

// ---------------- prep kernels ----------------
__global__ void pool_kernel(const float* __restrict__ memorys)
{
    size_t total = (size_t)RR * EE;
    for (size_t i = (size_t)blockIdx.x*blockDim.x + threadIdx.x; i < total;
         i += (size_t)gridDim.x*blockDim.x) {
        int e = (int)(i % EE);
        int tb = (int)(i / EE);
        int b = tb & (BB-1);
        int t = tb >> 6;
        const float* src = memorys + ((size_t)b*TMEL + 2*t)*EE + e;
        g_mem[i] = 0.5f*(src[0] + src[EE]);
    }
}

__global__ void di_kernel(const float* __restrict__ dec)
{
    size_t total = (size_t)RR * MMI;
    for (size_t i = (size_t)blockIdx.x*blockDim.x + threadIdx.x; i < total;
         i += (size_t)gridDim.x*blockDim.x) {
        int m = (int)(i % MMI);
        int tb = (int)(i / MMI);
        int b = tb & (BB-1);
        int t = tb >> 6;
        g_di[i] = (t == 0) ? 0.0f : dec[((size_t)b*TMEL + (2*t-1))*MMI + m];
    }
}

__global__ void add_kernel(const float* __restrict__ a, const float* __restrict__ b,
                           float* __restrict__ c, size_t n)
{
    for (size_t i = (size_t)blockIdx.x*blockDim.x + threadIdx.x; i < n;
         i += (size_t)gridDim.x*blockDim.x)
        c[i] = a[i] + b[i];
}

__device__ __forceinline__ uint32_t pack_bf2(float lo, float hi)
{
    __nv_bfloat162 t = __floats2bfloat162_rn(lo, hi);
    return *(uint32_t*)&t;
}

// A fragment pack: concat(A1,A2) -> per-lane m16k16 A frags (hi,lo uint4 pair)
__global__ void afrag_prep(const float* __restrict__ A1, int K1,
                           const float* __restrict__ A2, int K2, int nc)
{
    const int K = K1 + K2;
    size_t total = (size_t)NRB * nc * 512;
    for (size_t idx = (size_t)blockIdx.x*blockDim.x + threadIdx.x; idx < total;
         idx += (size_t)gridDim.x*blockDim.x) {
        int lane = (int)(idx & 31);
        int mt   = (int)((idx >> 5) & 7);
        int ks   = (int)((idx >> 8) & 1);
        size_t r = idx >> 9;
        int ci = (int)(r % nc);
        int rb = (int)(r / nc);
        int row = rb*128 + mt*16 + (lane >> 2);
        int k   = ci*32 + ks*16 + (lane & 3)*2;

        float v[8];
#pragma unroll
        for (int e = 0; e < 8; e++) {
            int rr_ = row + ((e >> 1) & 1)*8;          // e: {r0c0,r0c1? no: see order below}
            v[e] = 0.0f;
        }
        // order: 0:(r,k) 1:(r,k+1) 2:(r+8,k) 3:(r+8,k+1) 4:(r,k+8) 5:(r,k+9) 6:(r+8,k+8) 7:(r+8,k+9)
        int rows2[2] = {row, row + 8};
        int cols2[2] = {k, k + 8};
#pragma unroll
        for (int rI = 0; rI < 2; rI++)
#pragma unroll
            for (int cI = 0; cI < 2; cI++)
#pragma unroll
                for (int h2 = 0; h2 < 2; h2++) {
                    int kk = cols2[cI] + h2;
                    float val = 0.0f;
                    if (kk < K1)          val = A1[(size_t)rows2[rI]*K1 + kk];
                    else if (kk < K)      val = A2[(size_t)rows2[rI]*K2 + (kk - K1)];
                    v[cI*4 + rI*2 + h2] = val;
                }
        // v: 0:(r,k) 1:(r,k+1) 2:(r+8,k) 3:(r+8,k+1) 4:(r,k+8) 5:(r,k+9) 6:(r+8,k+8) 7:(r+8,k+9)
        uint4 hi, lo;
        float t0,t1;
        t0 = __bfloat162float(__float2bfloat16(v[0])); t1 = __bfloat162float(__float2bfloat16(v[1]));
        hi.x = pack_bf2(v[0], v[1]); lo.x = pack_bf2(v[0]-t0, v[1]-t1);
        t0 = __bfloat162float(__float2bfloat16(v[2])); t1 = __bfloat162float(__float2bfloat16(v[3]));
        hi.y = pack_bf2(v[2], v[3]); lo.y = pack_bf2(v[2]-t0, v[3]-t1);
        t0 = __bfloat162float(__float2bfloat16(v[4])); t1 = __bfloat162float(__float2bfloat16(v[5]));
        hi.z = pack_bf2(v[4], v[5]); lo.z = pack_bf2(v[4]-t0, v[5]-t1);
        t0 = __bfloat162float(__float2bfloat16(v[6])); t1 = __bfloat162float(__float2bfloat16(v[7]));
        hi.w = pack_bf2(v[6], v[7]); lo.w = pack_bf2(v[6]-t0, v[7]-t1);

        size_t base = ((size_t)rb*nc + ci)*1024;
        int entry = (ks*8 + mt)*32 + lane;
        g_Afrag[base + entry*2    ] = hi;
        g_Afrag[base + entry*2 + 1] = lo;
    }
}

// W fragment pack: W[N][K] -> per-lane n8k16 B frags {bh0,bh1,bl0,bl1}
__global__ void wfrag2_prep(const float* __restrict__ W, int N, int K, int nb, int nc)
{
    size_t total = (size_t)nb * nc * 1024;
    for (size_t idx = (size_t)blockIdx.x*blockDim.x + threadIdx.x; idx < total;
         idx += (size_t)gridDim.x*blockDim.x) {
        int lane  = (int)(idx & 31);
        int ntile = (int)((idx >> 5) & 15);
        int ks    = (int)((idx >> 9) & 1);
        size_t r  = idx >> 10;
        int ci = (int)(r % nc);
        int nbk = (int)(r / nc);
        int n = nbk*128 + ntile*8 + (lane >> 2);
        int k = ci*32 + ks*16 + (lane & 3)*2;
        float v0=0.f, v1=0.f, v2=0.f, v3=0.f;
        if (n < N) {
            if (k   < K) v0 = W[(size_t)n*K + k];
            if (k+1 < K) v1 = W[(size_t)n*K + k+1];
            if (k+8 < K) v2 = W[(size_t)n*K + k+8];
            if (k+9 < K) v3 = W[(size_t)n*K + k+9];
        }
        float h0 = __bfloat162float(__float2bfloat16(v0));
        float h1 = __bfloat162float(__float2bfloat16(v1));
        float h2 = __bfloat162float(__float2bfloat16(v2));
        float h3 = __bfloat162float(__float2bfloat16(v3));
        uint4 o;
        o.x = pack_bf2(v0, v1);
        o.y = pack_bf2(v2, v3);
        o.z = pack_bf2(v0 - h0, v1 - h1);
        o.w = pack_bf2(v2 - h2, v3 - h3);
        g_Wfrag2[((size_t)nbk*nc + ci)*1024 + (ks*16 + ntile)*32 + lane] = o;
    }
}

// pack whh into per-lane B fragments (verified)
__global__ void wfrag_prep(const float* __restrict__ whh)
{
    size_t idx = (size_t)blockIdx.x*blockDim.x + threadIdx.x;
    if (idx >= (size_t)128*8*8*3*32) return;
    int lane = (int)(idx & 31);
    size_t r1 = idx >> 5;
    int nt = (int)(r1 % 3);
    size_t r2 = r1 / 3;
    int q = (int)(r2 & 7);
    int w = (int)((r2 >> 3) & 7);
    int c = (int)(r2 >> 6);
    int gid = lane >> 2, tig = lane & 3;
    const float* wp = whh + (size_t)(nt*HH + c*8 + gid)*HH + w*128 + q*16;
    float v0 = wp[2*tig], v1 = wp[2*tig+1], v2 = wp[2*tig+8], v3 = wp[2*tig+9];
    float h0 = __bfloat162float(__float2bfloat16(v0));
    float h1 = __bfloat162float(__float2bfloat16(v1));
    float h2 = __bfloat162float(__float2bfloat16(v2));
    float h3 = __bfloat162float(__float2bfloat16(v3));
    uint4 o;
    o.x = pack_bf2(v0, v1);
    o.y = pack_bf2(v2, v3);
    o.z = pack_bf2(v0 - h0, v1 - h1);
    o.w = pack_bf2(v2 - h2, v3 - h3);
    g_wfrag[idx] = o;
}

__global__ void hfrag_zero()
{
    int i = blockIdx.x*blockDim.x + threadIdx.x;
    if (i < 4*64*64) g_hfrag[i] = make_uint4(0u,0u,0u,0u);
}

// ---------------- mma primitives ----------------
__device__ __forceinline__ void mma16816(float* c,
    uint32_t a0, uint32_t a1, uint32_t a2, uint32_t a3,
    uint32_t b0, uint32_t b1)
{
    asm volatile(
        "mma.sync.aligned.m16n8k16.row.col.f32.bf16.bf16.f32 "
        "{%0,%1,%2,%3}, {%4,%5,%6,%7}, {%8,%9}, {%0,%1,%2,%3};"
        : "+f"(c[0]), "+f"(c[1]), "+f"(c[2]), "+f"(c[3])
        : "r"(a0), "r"(a1), "r"(a2), "r"(a3), "r"(b0), "r"(b1));
}

__device__ __forceinline__ uint32_t smem_u32(const void* p) {
    uint32_t a;
    asm("{ .reg .u64 t; cvta.to.shared.u64 t, %1; cvt.u32.u64 %0, t; }" : "=r"(a) : "l"(p));
    return a;
}
#define CP_ASYNC16(dst, src) \
    asm volatile("cp.async.cg.shared.global [%0], [%1], 16;" :: "r"(dst), "l"(src) : "memory")
#define CP_COMMIT() asm volatile("cp.async.commit_group;" ::: "memory")
#define CP_WAIT(n)  asm volatile("cp.async.wait_group %0;" :: "n"(n) : "memory")

// ---------------- tensor-core batch GEMM, frag-packed, 3-stage cp.async ----------------
#define STAGE3_B 32768                 // A 16 KB + W 16 KB
#define NST3     3
#define GEMM3_SMEM (NST3*STAGE3_B)     // 98304

__global__ __launch_bounds__(256, 2)
void gemm_mma3(int nc, int N, const float* __restrict__ bias,
               float* __restrict__ C, int doRelu, int outBT)
{
    extern __shared__ char dynsm[];
    const int tid = threadIdx.x;
    const int lane = tid & 31, wid = tid >> 5;
    const int wm = wid >> 1, wn = wid & 1;
    const int g = lane >> 2, tg = lane & 3;
    const int row0 = blockIdx.y * 128;
    const int n0   = blockIdx.x * 128;

    const uint4* Asrc = g_Afrag  + (size_t)blockIdx.y*nc*1024;
    const uint4* Wsrc = g_Wfrag2 + (size_t)blockIdx.x*nc*1024;
    const uint32_t sb = smem_u32(dynsm);

    auto issue_stage = [&](int st, int ci) {
        uint32_t dstA = sb + st*STAGE3_B        + tid*16;
        uint32_t dstW = sb + st*STAGE3_B + 16384 + tid*16;
        const uint4* sa = Asrc + (size_t)ci*1024 + tid;
        const uint4* sw = Wsrc + (size_t)ci*1024 + tid;
#pragma unroll
        for (int u = 0; u < 4; u++) {
            CP_ASYNC16(dstA + u*4096, sa + u*256);
            CP_ASYNC16(dstW + u*4096, sw + u*256);
        }
        CP_COMMIT();
    };

    float acc[2][8][4];
#pragma unroll
    for (int mt = 0; mt < 2; mt++)
#pragma unroll
        for (int nt = 0; nt < 8; nt++)
#pragma unroll
            for (int r = 0; r < 4; r++) acc[mt][nt][r] = 0.0f;

    issue_stage(0, 0);
    issue_stage(1, 1);

    int st = 0;
    for (int i = 0; i < nc; i++) {
        if (i == nc - 1) { CP_WAIT(0); } else { CP_WAIT(1); }
        __syncthreads();
        if (i + NST3 - 1 < nc) {
            int ist = st + 2; if (ist >= NST3) ist -= NST3;
            issue_stage(ist, i + NST3 - 1);
        }

        const uint4* sA = (const uint4*)(dynsm + st*STAGE3_B);
        const uint4* sW = (const uint4*)(dynsm + st*STAGE3_B + 16384);

#pragma unroll
        for (int ks = 0; ks < 2; ks++) {
            uint4 ah[2], al[2];
#pragma unroll
            for (int mt = 0; mt < 2; mt++) {
                int entry = (ks*8 + wm*2 + mt)*32 + lane;
                ah[mt] = sA[entry*2];
                al[mt] = sA[entry*2 + 1];
            }
#pragma unroll
            for (int nt = 0; nt < 8; nt++) {
                uint4 bw = sW[(ks*16 + wn*8 + nt)*32 + lane];
#pragma unroll
                for (int mt = 0; mt < 2; mt++) {
                    mma16816(acc[mt][nt], ah[mt].x, ah[mt].y, ah[mt].z, ah[mt].w, bw.x, bw.y);
                    mma16816(acc[mt][nt], ah[mt].x, ah[mt].y, ah[mt].z, ah[mt].w, bw.z, bw.w);
                    mma16816(acc[mt][nt], al[mt].x, al[mt].y, al[mt].z, al[mt].w, bw.x, bw.y);
                }
            }
        }
        if (++st == NST3) st = 0;
    }

    // epilogue (verified mapping)
#pragma unroll
    for (int mt = 0; mt < 2; mt++) {
        int mrow0 = row0 + wm*32 + mt*16 + g;
#pragma unroll
        for (int nt = 0; nt < 8; nt++) {
            int col = n0 + wn*64 + nt*8 + tg*2;
#pragma unroll
            for (int r = 0; r < 4; r++) {
                int m = mrow0 + (r >> 1)*8;
                int n = col + (r & 1);
                if (n < N) {
                    float v = acc[mt][nt][r] + bias[n];
                    if (doRelu) v = fmaxf(v, 0.0f);
                    if (outBT) {
                        int t = m >> 6, b = m & (BB-1);
                        C[((size_t)b*TD + t)*N + n] = v;
                    } else {
                        C[(size_t)m*N + n] = v;
                    }
                }
            }
        }
    }
}

// ---------------- persistent mma.sync GRU recurrence (smem-resident weights) ----------------
__device__ __forceinline__ float sigmoidf(float x) { return 1.0f/(1.0f + expf(-x)); }

__device__ __forceinline__ void grid_barrier()
{
    __threadfence();
    __syncthreads();
    if (threadIdx.x == 0) {
        unsigned g = *(volatile unsigned*)&g_bargen;
        unsigned old = atomicAdd(&g_barcnt, 1u);
        if (old == GRU_NBLK - 1u) {
            atomicExch(&g_barcnt, 0u);
            __threadfence();
            atomicAdd(&g_bargen, 1u);
        } else {
            while (*(volatile unsigned*)&g_bargen == g) { }
        }
        __threadfence();
    }
    __syncthreads();
}

#define GRU_SMEM3 (98304 + 49152)   // wsm (6144 uint4) + sred (12288 f32)

__global__ __launch_bounds__(256, 1)
void gru_pass(int pass, const float* __restrict__ bhh)
{
    float* hall = (pass == 0) ? g_h1 : (pass == 1) ? g_h2 : g_h3;
    extern __shared__ char gsm[];
    uint4* wsm  = (uint4*)gsm;                  // [ (wid*8+q)*3+nt ][lane]
    float* sred = (float*)(gsm + 98304);
    const int tid = threadIdx.x, wid = tid >> 5, lane = tid & 31;
    const int c = blockIdx.x;

    // preload this CTA's weight fragments once
    {
        const uint4* src = g_wfrag + (size_t)c*6144;
        for (int i = tid; i < 6144; i += 256) wsm[i] = src[i];
    }
    __syncthreads();

    for (int t = 0; t < TD; t++) {
        const int par = t & 1;
        const uint4* hbase = g_hfrag + (size_t)par*4*64*64;

        float acc[4][3][4];
#pragma unroll
        for (int m = 0; m < 4; m++)
#pragma unroll
            for (int nt = 0; nt < 3; nt++)
#pragma unroll
                for (int r = 0; r < 4; r++) acc[m][nt][r] = 0.0f;

#pragma unroll 2
        for (int q = 0; q < 8; q++) {
            const int s = wid*8 + q;
            uint4 ah[4], al[4];
#pragma unroll
            for (int m = 0; m < 4; m++) {
                const uint4* p = hbase + ((size_t)m*64 + s)*64 + lane*2;
                ah[m] = p[0];
                al[m] = p[1];
            }
            uint4 bw[3];
#pragma unroll
            for (int nt = 0; nt < 3; nt++)
                bw[nt] = wsm[((wid*8 + q)*3 + nt)*32 + lane];
#pragma unroll
            for (int m = 0; m < 4; m++)
#pragma unroll
                for (int nt = 0; nt < 3; nt++) {
                    mma16816(acc[m][nt], ah[m].x, ah[m].y, ah[m].z, ah[m].w, bw[nt].x, bw[nt].y);
                    mma16816(acc[m][nt], ah[m].x, ah[m].y, ah[m].z, ah[m].w, bw[nt].z, bw[nt].w);
                    mma16816(acc[m][nt], al[m].x, al[m].y, al[m].z, al[m].w, bw[nt].x, bw[nt].y);
                }
        }
#pragma unroll
        for (int m = 0; m < 4; m++)
#pragma unroll
            for (int nt = 0; nt < 3; nt++)
#pragma unroll
                for (int r = 0; r < 4; r++)
                    sred[(((wid*4 + m)*3 + nt)*4 + r)*32 + lane] = acc[m][nt][r];
        __syncthreads();

        const int par2 = (t + 1) & 1;
        for (int o = tid; o < 512; o += 256) {
            int b = o >> 3, j = o & 7;
            int jg = c*8 + j;
            int m = b >> 4;
            int rowhi = (b >> 3) & 1;
            int lo_ = (b & 7)*4 + (j >> 1);
            int rc = rowhi*2 + (j & 1);
            float gsum[3];
#pragma unroll
            for (int nt = 0; nt < 3; nt++) {
                float s_ = 0.0f;
#pragma unroll
                for (int w = 0; w < 8; w++)
                    s_ += sred[(((w*4 + m)*3 + nt)*4 + rc)*32 + lo_];
                gsum[nt] = s_;
            }
            const float* gib = g_gi + ((size_t)t*BB + b)*3*HH;
            float rr = sigmoidf(gib[jg]        + gsum[0] + bhh[jg]);
            float zz = sigmoidf(gib[HH + jg]   + gsum[1] + bhh[HH + jg]);
            float nn = tanhf   (gib[2*HH + jg] + rr*(gsum[2] + bhh[2*HH + jg]));
            float hp = (t > 0) ? hall[((size_t)(t-1)*BB + b)*HH + jg] : 0.0f;
            float h  = (1.0f - zz)*nn + zz*hp;
            hall[((size_t)t*BB + b)*HH + jg] = h;

            __nv_bfloat16 hhi = __float2bfloat16(h);
            __nv_bfloat16 hlo = __float2bfloat16(h - __bfloat162float(hhi));
            int s = jg >> 4;
            int colhi = c & 1;
            int reg = rowhi + 2*colhi;
            uint8_t* base = (uint8_t*)g_hfrag
                + (((size_t)par2*4 + m)*64 + s)*1024 + lo_*32;
            *(__nv_bfloat16*)(base + reg*4 + (j & 1)*2)      = hhi;
            *(__nv_bfloat16*)(base + 16 + reg*4 + (j & 1)*2) = hlo;
        }
        grid_barrier();
    }
}

// ---------------- host orchestration ----------------
extern "C" void kernel_launch(void* const* d_in, const int* in_sizes, int n_in,
                              void* d_out, int out_size)
{
    const float* memorys = (const float*)d_in[0];
    const float* dec     = (const float*)d_in[1];
    const float* pre_w1 = (const float*)d_in[3];
    const float* pre_b1 = (const float*)d_in[4];
    const float* pre_w2 = (const float*)d_in[5];
    const float* pre_b2 = (const float*)d_in[6];
    const float* g1_wih = (const float*)d_in[7];
    const float* g1_whh = (const float*)d_in[8];
    const float* g1_bih = (const float*)d_in[9];
    const float* g1_bhh = (const float*)d_in[10];
    const float* att_w  = (const float*)d_in[11];
    const float* att_b  = (const float*)d_in[12];
    const float* g2_wih = (const float*)d_in[13];
    const float* g2_whh = (const float*)d_in[14];
    const float* g2_bih = (const float*)d_in[15];
    const float* g2_bhh = (const float*)d_in[16];
    const float* g3_wih = (const float*)d_in[17];
    const float* g3_whh = (const float*)d_in[18];
    const float* g3_bih = (const float*)d_in[19];
    const float* g3_bhh = (const float*)d_in[20];
    const float* proj_w = (const float*)d_in[21];
    const float* proj_b = (const float*)d_in[22];
    float* out = (float*)d_out;

    float *p_di,*p_mem,*p_xa,*p_xb,*p_gi,*p_h1,*p_h2,*p_h3,*p_d2,*p_r2;
    cudaGetSymbolAddress((void**)&p_di,  g_di);
    cudaGetSymbolAddress((void**)&p_mem, g_mem);
    cudaGetSymbolAddress((void**)&p_xa,  g_xa);
    cudaGetSymbolAddress((void**)&p_xb,  g_xb);
    cudaGetSymbolAddress((void**)&p_gi,  g_gi);
    cudaGetSymbolAddress((void**)&p_h1,  g_h1);
    cudaGetSymbolAddress((void**)&p_h2,  g_h2);
    cudaGetSymbolAddress((void**)&p_h3,  g_h3);
    cudaGetSymbolAddress((void**)&p_d2,  g_d2);
    cudaGetSymbolAddress((void**)&p_r2,  g_r2);

    cudaFuncSetAttribute(gemm_mma3, cudaFuncAttributeMaxDynamicSharedMemorySize, GEMM3_SMEM);
    cudaFuncSetAttribute(gru_pass,  cudaFuncAttributeMaxDynamicSharedMemorySize, GRU_SMEM3);

    pool_kernel<<<4096, 256>>>(memorys);
    di_kernel  <<<4096, 256>>>(dec);

    auto gemm = [&](const float* A1, int K1, const float* A2, int K2,
                    const float* W, const float* b, float* C, int N,
                    int relu, int bt) {
        int K = K1 + K2;
        int Kce = (K + 31) & ~31;
        int Nce = (N + 127) & ~127;
        int nc = Kce / 32;
        int nb = Nce / 128;
        afrag_prep<<<8192, 256>>>(A1, K1, A2, K2, nc);
        wfrag2_prep<<<2048, 256>>>(W, N, K, nb, nc);
        dim3 grid(nb, NRB);
        gemm_mma3<<<grid, 256, GEMM3_SMEM>>>(nc, N, b, C, relu, bt);
    };

    // prenet
    gemm(p_di, MMI, nullptr, 0, pre_w1, pre_b1, p_xa, PP, 1, 0);
    gemm(p_xa, PP,  nullptr, 0, pre_w2, pre_b2, p_xb, PP, 1, 0);

    // GRU1
    gemm(p_xb, PP, p_mem, EE, g1_wih, g1_bih, p_gi, 3*HH, 0, 0);
    wfrag_prep<<<3072, 256>>>(g1_whh);
    hfrag_zero<<<64, 256>>>();
    gru_pass<<<GRU_NBLK, 256, GRU_SMEM3>>>(0, g1_bhh);

    // attention linear + GRU2
    gemm(p_h1, HH, p_mem, EE, att_w, att_b, p_d2, HH, 0, 0);
    gemm(p_d2, HH, nullptr, 0, g2_wih, g2_bih, p_gi, 3*HH, 0, 0);
    wfrag_prep<<<3072, 256>>>(g2_whh);
    hfrag_zero<<<64, 256>>>();
    gru_pass<<<GRU_NBLK, 256, GRU_SMEM3>>>(1, g2_bhh);

    // r2 = h2 + d2
    add_kernel<<<8192, 256>>>(p_h2, p_d2, p_r2, (size_t)RR*HH);

    // GRU3
    gemm(p_r2, HH, nullptr, 0, g3_wih, g3_bih, p_gi, 3*HH, 0, 0);
    wfrag_prep<<<3072, 256>>>(g3_whh);
    hfrag_zero<<<64, 256>>>();
    gru_pass<<<GRU_NBLK, 256, GRU_SMEM3>>>(2, g3_bhh);

    // r3 = h3 + r2
    add_kernel<<<8192, 256>>>(p_h3, p_r2, p_d2, (size_t)RR*HH);

    // projection into [B,T,160]
    gemm(p_d2, HH, p_mem, EE, proj_w, proj_b, out, MMI*2, 0, 1);
}